// round 2
// baseline (speedup 1.0000x reference)
#include <cuda_runtime.h>
#include <cuda_bf16.h>
#include <cstdint>
#include <cstdio>

typedef __nv_bfloat16 bf16;

#define DIMV 768
#define HIDV 2048
#define TOKV 4096
#define NEXP 8
#define MAXTILE 40
#define MAXROWS (MAXTILE*128)

#define BM 128
#define BN 64
#define BK 32
#define SROW 40   // BK + 8 bf16 pad -> 80B row stride, conflict-free

// ------------------------- device scratch ---------------------------------
__device__ bf16 gW1h[(size_t)NEXP*HIDV*DIMV];
__device__ bf16 gW1l[(size_t)NEXP*HIDV*DIMV];
__device__ bf16 gW2h[(size_t)NEXP*HIDV*DIMV];
__device__ bf16 gW2l[(size_t)NEXP*HIDV*DIMV];
__device__ bf16 gW3h[(size_t)NEXP*DIMV*HIDV];
__device__ bf16 gW3l[(size_t)NEXP*DIMV*HIDV];
__device__ bf16 gXh[(size_t)MAXROWS*DIMV];
__device__ bf16 gXl[(size_t)MAXROWS*DIMV];
__device__ bf16 gUh[(size_t)MAXROWS*HIDV];
__device__ bf16 gUl[(size_t)MAXROWS*HIDV];
__device__ int   gTokE[TOKV];
__device__ float gP[TOKV];
__device__ int   gRowTok[MAXROWS];
__device__ int   gTileE[MAXTILE];

// ------------------------- small helpers ----------------------------------
__device__ __forceinline__ void cpa16(void* s, const void* g) {
    unsigned sa = (unsigned)__cvta_generic_to_shared(s);
    asm volatile("cp.async.cg.shared.global [%0], [%1], 16;\n" :: "r"(sa), "l"(g));
}
__device__ __forceinline__ void cpcommit() {
    asm volatile("cp.async.commit_group;\n");
}
__device__ __forceinline__ void mma_bf16(float* c, const unsigned* a, const unsigned* b) {
    asm volatile(
        "mma.sync.aligned.m16n8k16.row.col.f32.bf16.bf16.f32 "
        "{%0,%1,%2,%3},{%4,%5,%6,%7},{%8,%9},{%0,%1,%2,%3};\n"
        : "+f"(c[0]), "+f"(c[1]), "+f"(c[2]), "+f"(c[3])
        : "r"(a[0]), "r"(a[1]), "r"(a[2]), "r"(a[3]), "r"(b[0]), "r"(b[1]));
}
__device__ __forceinline__ void split2(float v, bf16& h, bf16& l) {
    h = __float2bfloat16(v);
    l = __float2bfloat16(v - __bfloat162float(h));
}

// ------------------------- router ------------------------------------------
__global__ void router_k(const float* __restrict__ x,
                         const float* __restrict__ rw,
                         const float* __restrict__ rb) {
    int wid  = (blockIdx.x * blockDim.x + threadIdx.x) >> 5;
    int lane = threadIdx.x & 31;
    if (wid >= TOKV) return;
    const float* xr = x + (size_t)wid * DIMV;
    float acc[NEXP];
#pragma unroll
    for (int e = 0; e < NEXP; e++) acc[e] = 0.f;
    for (int k = lane; k < DIMV; k += 32) {
        float xv = xr[k];
        const float* w = rw + k * NEXP;
#pragma unroll
        for (int e = 0; e < NEXP; e++) acc[e] += xv * w[e];
    }
#pragma unroll
    for (int off = 16; off; off >>= 1)
#pragma unroll
        for (int e = 0; e < NEXP; e++)
            acc[e] += __shfl_xor_sync(0xffffffffu, acc[e], off);
    if (lane == 0) {
        float l[NEXP];
        float m = -1e30f; int mi = 0;
#pragma unroll
        for (int e = 0; e < NEXP; e++) {
            l[e] = acc[e] + rb[e];
            if (l[e] > m) { m = l[e]; mi = e; }
        }
        float s = 0.f;
#pragma unroll
        for (int e = 0; e < NEXP; e++) s += expf(l[e] - m);
        gTokE[wid] = mi;
        gP[wid] = 1.f / s;
    }
}

// ------------------------- plan (single block) ------------------------------
__global__ void plan_k() {
    __shared__ int cnt[NEXP], cur[NEXP], base[NEXP];
    int tid = threadIdx.x;
    if (tid < NEXP) { cnt[tid] = 0; cur[tid] = 0; }
    __syncthreads();
    for (int t = tid; t < TOKV; t += blockDim.x) atomicAdd(&cnt[gTokE[t]], 1);
    __syncthreads();
    if (tid == 0) {
        int acc = 0, tc = 0;
        for (int e = 0; e < NEXP; e++) {
            base[e] = acc;
            int nt = (cnt[e] + 127) >> 7;
            for (int i = 0; i < nt && tc < MAXTILE; i++) gTileE[tc++] = e;
            acc += nt * 128;
        }
        for (; tc < MAXTILE; tc++) gTileE[tc] = 0;
    }
    __syncthreads();
    for (int r = tid; r < MAXROWS; r += blockDim.x) gRowTok[r] = -1;
    __syncthreads();
    for (int t = tid; t < TOKV; t += blockDim.x) {
        int e = gTokE[t];
        int s = atomicAdd(&cur[e], 1);
        gRowTok[base[e] + s] = t;
    }
}

// ---------------- weight transpose + bf16 split ----------------------------
// src [E][R][C] f32  ->  dst hi/lo [E][C][R] bf16 (K-contiguous for GEMM)
__global__ void tsplit_k(const float* __restrict__ src, int R, int C, int which) {
    __shared__ float tile[32][33];
    bf16 *dh, *dl;
    if (which == 0)      { dh = gW1h; dl = gW1l; }
    else if (which == 1) { dh = gW2h; dl = gW2l; }
    else                 { dh = gW3h; dl = gW3l; }
    int e = blockIdx.z;
    int c0 = blockIdx.x * 32, r0 = blockIdx.y * 32;
    int tx = threadIdx.x, ty = threadIdx.y;
    const float* s = src + (size_t)e * R * C;
#pragma unroll
    for (int i = 0; i < 4; i++) {
        int r = r0 + ty + i * 8;
        tile[ty + i * 8][tx] = s[(size_t)r * C + c0 + tx];
    }
    __syncthreads();
    bf16* dhp = dh + (size_t)e * C * R;
    bf16* dlp = dl + (size_t)e * C * R;
#pragma unroll
    for (int i = 0; i < 4; i++) {
        int c = c0 + ty + i * 8;
        int r = r0 + tx;
        float v = tile[tx][ty + i * 8];
        bf16 h, l; split2(v, h, l);
        dhp[(size_t)c * R + r] = h;
        dlp[(size_t)c * R + r] = l;
    }
}

// ------------------------- gather X + split --------------------------------
__global__ void gather_k(const float* __restrict__ x) {
    int row = blockIdx.x;
    int tok = gRowTok[row];
    for (int k = threadIdx.x; k < DIMV; k += blockDim.x) {
        float v = (tok >= 0) ? x[(size_t)tok * DIMV + k] : 0.f;
        bf16 h, l; split2(v, h, l);
        gXh[(size_t)row * DIMV + k] = h;
        gXl[(size_t)row * DIMV + k] = l;
    }
}

// ------------------------- GEMM1: X @ W1/W2, fused SwiGLU ------------------
__device__ __forceinline__ void g1_load(
    bf16* a_h, bf16* a_l, bf16* b1h, bf16* b1l, bf16* b2h, bf16* b2l,
    const bf16* gAh, const bf16* gAl,
    const bf16* gB1h, const bf16* gB1l, const bf16* gB2h, const bf16* gB2l,
    int kc, int tid)
{
#pragma unroll
    for (int i = 0; i < 2; i++) {
        int q = tid * 2 + i, r = q >> 2, ko = (q & 3) * 8;
        size_t go = (size_t)r * DIMV + kc + ko;
        int so = r * SROW + ko;
        cpa16(a_h + so, gAh + go);
        cpa16(a_l + so, gAl + go);
    }
    {
        int r = tid >> 2, ko = (tid & 3) * 8;
        size_t go = (size_t)r * DIMV + kc + ko;
        int so = r * SROW + ko;
        cpa16(b1h + so, gB1h + go);
        cpa16(b1l + so, gB1l + go);
        cpa16(b2h + so, gB2h + go);
        cpa16(b2l + so, gB2l + go);
    }
    cpcommit();
}

__global__ __launch_bounds__(256, 1) void gemm1_k() {
    extern __shared__ bf16 sm[];
    bf16* Ah  = sm;
    bf16* Al  = Ah  + 2 * BM * SROW;
    bf16* B1h = Al  + 2 * BM * SROW;
    bf16* B1l = B1h + 2 * BN * SROW;
    bf16* B2h = B1l + 2 * BN * SROW;
    bf16* B2l = B2h + 2 * BN * SROW;

    int tile = blockIdx.y, nb0 = blockIdx.x * BN;
    int e = gTileE[tile];
    int tid = threadIdx.x, lane = tid & 31, warp = tid >> 5;
    int wm = warp & 3, wn = warp >> 2;
    int g = lane >> 2, t4 = lane & 3;

    const bf16* gAh  = gXh + (size_t)tile * BM * DIMV;
    const bf16* gAl  = gXl + (size_t)tile * BM * DIMV;
    const bf16* gB1h = gW1h + ((size_t)e * HIDV + nb0) * DIMV;
    const bf16* gB1l = gW1l + ((size_t)e * HIDV + nb0) * DIMV;
    const bf16* gB2h = gW2h + ((size_t)e * HIDV + nb0) * DIMV;
    const bf16* gB2l = gW2l + ((size_t)e * HIDV + nb0) * DIMV;

    float acc1[2][4][4], acc2[2][4][4];
#pragma unroll
    for (int m = 0; m < 2; m++)
#pragma unroll
        for (int n = 0; n < 4; n++)
#pragma unroll
            for (int i = 0; i < 4; i++) { acc1[m][n][i] = 0.f; acc2[m][n][i] = 0.f; }

    const int NSTEP = DIMV / BK;  // 24
    g1_load(Ah, Al, B1h, B1l, B2h, B2l, gAh, gAl, gB1h, gB1l, gB2h, gB2l, 0, tid);

    for (int s = 0; s < NSTEP; s++) {
        if (s + 1 < NSTEP) {
            int buf = (s + 1) & 1;
            g1_load(Ah + buf * BM * SROW, Al + buf * BM * SROW,
                    B1h + buf * BN * SROW, B1l + buf * BN * SROW,
                    B2h + buf * BN * SROW, B2l + buf * BN * SROW,
                    gAh, gAl, gB1h, gB1l, gB2h, gB2l, (s + 1) * BK, tid);
            asm volatile("cp.async.wait_group 1;\n");
        } else {
            asm volatile("cp.async.wait_group 0;\n");
        }
        __syncthreads();
        int buf = s & 1;
        const bf16* a_h = Ah  + buf * BM * SROW;
        const bf16* a_l = Al  + buf * BM * SROW;
        const bf16* b1h = B1h + buf * BN * SROW;
        const bf16* b1l = B1l + buf * BN * SROW;
        const bf16* b2h = B2h + buf * BN * SROW;
        const bf16* b2l = B2l + buf * BN * SROW;

#pragma unroll
        for (int kk = 0; kk < 2; kk++) {
            int kb = kk * 16;
            unsigned Afh[2][4], Afl[2][4];
#pragma unroll
            for (int mt = 0; mt < 2; mt++) {
                int rb = wm * 32 + mt * 16 + g;
                const bf16* p = a_h + rb * SROW + kb + t4 * 2;
                Afh[mt][0] = *(const unsigned*)(p);
                Afh[mt][1] = *(const unsigned*)(p + 8 * SROW);
                Afh[mt][2] = *(const unsigned*)(p + 8);
                Afh[mt][3] = *(const unsigned*)(p + 8 * SROW + 8);
                const bf16* q = a_l + rb * SROW + kb + t4 * 2;
                Afl[mt][0] = *(const unsigned*)(q);
                Afl[mt][1] = *(const unsigned*)(q + 8 * SROW);
                Afl[mt][2] = *(const unsigned*)(q + 8);
                Afl[mt][3] = *(const unsigned*)(q + 8 * SROW + 8);
            }
            // W1
            {
                unsigned Bh[4][2], Bl[4][2];
#pragma unroll
                for (int nt = 0; nt < 4; nt++) {
                    int nr = wn * 32 + nt * 8 + g;
                    const bf16* p = b1h + nr * SROW + kb + t4 * 2;
                    Bh[nt][0] = *(const unsigned*)(p);
                    Bh[nt][1] = *(const unsigned*)(p + 8);
                    const bf16* q = b1l + nr * SROW + kb + t4 * 2;
                    Bl[nt][0] = *(const unsigned*)(q);
                    Bl[nt][1] = *(const unsigned*)(q + 8);
                }
#pragma unroll
                for (int mt = 0; mt < 2; mt++)
#pragma unroll
                    for (int nt = 0; nt < 4; nt++) {
                        mma_bf16(acc1[mt][nt], Afh[mt], Bh[nt]);
                        mma_bf16(acc1[mt][nt], Afh[mt], Bl[nt]);
                        mma_bf16(acc1[mt][nt], Afl[mt], Bh[nt]);
                    }
            }
            // W2
            {
                unsigned Bh[4][2], Bl[4][2];
#pragma unroll
                for (int nt = 0; nt < 4; nt++) {
                    int nr = wn * 32 + nt * 8 + g;
                    const bf16* p = b2h + nr * SROW + kb + t4 * 2;
                    Bh[nt][0] = *(const unsigned*)(p);
                    Bh[nt][1] = *(const unsigned*)(p + 8);
                    const bf16* q = b2l + nr * SROW + kb + t4 * 2;
                    Bl[nt][0] = *(const unsigned*)(q);
                    Bl[nt][1] = *(const unsigned*)(q + 8);
                }
#pragma unroll
                for (int mt = 0; mt < 2; mt++)
#pragma unroll
                    for (int nt = 0; nt < 4; nt++) {
                        mma_bf16(acc2[mt][nt], Afh[mt], Bh[nt]);
                        mma_bf16(acc2[mt][nt], Afh[mt], Bl[nt]);
                        mma_bf16(acc2[mt][nt], Afl[mt], Bh[nt]);
                    }
            }
        }
        __syncthreads();
    }

    // epilogue: u = silu(h1)*h2, split to bf16 hi/lo, store
#pragma unroll
    for (int mt = 0; mt < 2; mt++) {
#pragma unroll
        for (int nt = 0; nt < 4; nt++) {
            int lr = wm * 32 + mt * 16 + g;
            int grow = tile * 128 + lr;
            int col = nb0 + wn * 32 + nt * 8 + t4 * 2;
            const float* c1 = acc1[mt][nt];
            const float* c2 = acc2[mt][nt];
#pragma unroll
            for (int half = 0; half < 2; half++) {
                int r = grow + half * 8;
                float h1a = c1[half * 2 + 0], h1b = c1[half * 2 + 1];
                float h2a = c2[half * 2 + 0], h2b = c2[half * 2 + 1];
                float ua = h1a * (1.f / (1.f + expf(-h1a))) * h2a;
                float ub = h1b * (1.f / (1.f + expf(-h1b))) * h2b;
                bf16 ha, la, hb, lb;
                split2(ua, ha, la);
                split2(ub, hb, lb);
                __nv_bfloat162 vh; vh.x = ha; vh.y = hb;
                __nv_bfloat162 vl; vl.x = la; vl.y = lb;
                *(__nv_bfloat162*)(gUh + (size_t)r * HIDV + col) = vh;
                *(__nv_bfloat162*)(gUl + (size_t)r * HIDV + col) = vl;
            }
        }
    }
}

// ------------------------- GEMM2: U @ W3, combine epilogue -----------------
__device__ __forceinline__ void g2_load(
    bf16* a_h, bf16* a_l, bf16* bh, bf16* bl,
    const bf16* gAh, const bf16* gAl, const bf16* gBh, const bf16* gBl,
    int kc, int tid)
{
#pragma unroll
    for (int i = 0; i < 2; i++) {
        int q = tid * 2 + i, r = q >> 2, ko = (q & 3) * 8;
        size_t go = (size_t)r * HIDV + kc + ko;
        int so = r * SROW + ko;
        cpa16(a_h + so, gAh + go);
        cpa16(a_l + so, gAl + go);
    }
    {
        int r = tid >> 2, ko = (tid & 3) * 8;
        size_t go = (size_t)r * HIDV + kc + ko;
        int so = r * SROW + ko;
        cpa16(bh + so, gBh + go);
        cpa16(bl + so, gBl + go);
    }
    cpcommit();
}

__global__ __launch_bounds__(256, 1) void gemm2_k(float* __restrict__ out) {
    extern __shared__ bf16 sm[];
    bf16* Ah = sm;
    bf16* Al = Ah + 2 * BM * SROW;
    bf16* Bh = Al + 2 * BM * SROW;
    bf16* Bl = Bh + 2 * BN * SROW;

    int tile = blockIdx.y, nb0 = blockIdx.x * BN;
    int e = gTileE[tile];
    int tid = threadIdx.x, lane = tid & 31, warp = tid >> 5;
    int wm = warp & 3, wn = warp >> 2;
    int g = lane >> 2, t4 = lane & 3;

    const bf16* gAh2 = gUh + (size_t)tile * BM * HIDV;
    const bf16* gAl2 = gUl + (size_t)tile * BM * HIDV;
    const bf16* gBh2 = gW3h + ((size_t)e * DIMV + nb0) * HIDV;
    const bf16* gBl2 = gW3l + ((size_t)e * DIMV + nb0) * HIDV;

    float acc[2][4][4];
#pragma unroll
    for (int m = 0; m < 2; m++)
#pragma unroll
        for (int n = 0; n < 4; n++)
#pragma unroll
            for (int i = 0; i < 4; i++) acc[m][n][i] = 0.f;

    const int NSTEP = HIDV / BK;  // 64
    g2_load(Ah, Al, Bh, Bl, gAh2, gAl2, gBh2, gBl2, 0, tid);

    for (int s = 0; s < NSTEP; s++) {
        if (s + 1 < NSTEP) {
            int buf = (s + 1) & 1;
            g2_load(Ah + buf * BM * SROW, Al + buf * BM * SROW,
                    Bh + buf * BN * SROW, Bl + buf * BN * SROW,
                    gAh2, gAl2, gBh2, gBl2, (s + 1) * BK, tid);
            asm volatile("cp.async.wait_group 1;\n");
        } else {
            asm volatile("cp.async.wait_group 0;\n");
        }
        __syncthreads();
        int buf = s & 1;
        const bf16* a_h = Ah + buf * BM * SROW;
        const bf16* a_l = Al + buf * BM * SROW;
        const bf16* b_h = Bh + buf * BN * SROW;
        const bf16* b_l = Bl + buf * BN * SROW;

#pragma unroll
        for (int kk = 0; kk < 2; kk++) {
            int kb = kk * 16;
            unsigned Afh[2][4], Afl[2][4];
#pragma unroll
            for (int mt = 0; mt < 2; mt++) {
                int rb = wm * 32 + mt * 16 + g;
                const bf16* p = a_h + rb * SROW + kb + t4 * 2;
                Afh[mt][0] = *(const unsigned*)(p);
                Afh[mt][1] = *(const unsigned*)(p + 8 * SROW);
                Afh[mt][2] = *(const unsigned*)(p + 8);
                Afh[mt][3] = *(const unsigned*)(p + 8 * SROW + 8);
                const bf16* q = a_l + rb * SROW + kb + t4 * 2;
                Afl[mt][0] = *(const unsigned*)(q);
                Afl[mt][1] = *(const unsigned*)(q + 8 * SROW);
                Afl[mt][2] = *(const unsigned*)(q + 8);
                Afl[mt][3] = *(const unsigned*)(q + 8 * SROW + 8);
            }
            unsigned Bfh[4][2], Bfl[4][2];
#pragma unroll
            for (int nt = 0; nt < 4; nt++) {
                int nr = wn * 32 + nt * 8 + g;
                const bf16* p = b_h + nr * SROW + kb + t4 * 2;
                Bfh[nt][0] = *(const unsigned*)(p);
                Bfh[nt][1] = *(const unsigned*)(p + 8);
                const bf16* q = b_l + nr * SROW + kb + t4 * 2;
                Bfl[nt][0] = *(const unsigned*)(q);
                Bfl[nt][1] = *(const unsigned*)(q + 8);
            }
#pragma unroll
            for (int mt = 0; mt < 2; mt++)
#pragma unroll
                for (int nt = 0; nt < 4; nt++) {
                    mma_bf16(acc[mt][nt], Afh[mt], Bfh[nt]);
                    mma_bf16(acc[mt][nt], Afh[mt], Bfl[nt]);
                    mma_bf16(acc[mt][nt], Afl[mt], Bfh[nt]);
                }
        }
        __syncthreads();
    }

    // epilogue: bf16-cast, multiply by prob, scatter by token
#pragma unroll
    for (int mt = 0; mt < 2; mt++) {
        int lr = wm * 32 + mt * 16 + g;
        int grow = tile * 128 + lr;
        int tokA = gRowTok[grow];
        int tokB = gRowTok[grow + 8];
        float pA = (tokA >= 0) ? gP[tokA] : 0.f;
        float pB = (tokB >= 0) ? gP[tokB] : 0.f;
#pragma unroll
        for (int nt = 0; nt < 4; nt++) {
            int col = nb0 + wn * 32 + nt * 8 + t4 * 2;
            const float* c = acc[mt][nt];
            if (tokA >= 0) {
                out[(size_t)tokA * DIMV + col]     = __bfloat162float(__float2bfloat16(c[0])) * pA;
                out[(size_t)tokA * DIMV + col + 1] = __bfloat162float(__float2bfloat16(c[1])) * pA;
            }
            if (tokB >= 0) {
                out[(size_t)tokB * DIMV + col]     = __bfloat162float(__float2bfloat16(c[2])) * pB;
                out[(size_t)tokB * DIMV + col + 1] = __bfloat162float(__float2bfloat16(c[3])) * pB;
            }
        }
    }
}

// ------------------------- launcher ----------------------------------------
extern "C" void kernel_launch(void* const* d_in, const int* in_sizes, int n_in,
                              void* d_out, int out_size) {
    const float* x  = (const float*)d_in[0];
    const float* rw = (const float*)d_in[1];
    const float* rb = (const float*)d_in[2];
    const float* w1 = (const float*)d_in[3];
    const float* w2 = (const float*)d_in[4];
    const float* w3 = (const float*)d_in[5];
    float* out = (float*)d_out;

    const int SM1 = (int)((2 * BM * SROW * 2 + 2 * BN * SROW * 4) * sizeof(bf16)); // 81920
    const int SM2 = (int)((2 * BM * SROW * 2 + 2 * BN * SROW * 2) * sizeof(bf16)); // 61440
    cudaFuncSetAttribute(gemm1_k, cudaFuncAttributeMaxDynamicSharedMemorySize, SM1);
    cudaFuncSetAttribute(gemm2_k, cudaFuncAttributeMaxDynamicSharedMemorySize, SM2);

    router_k<<<TOKV / 8, 256>>>(x, rw, rb);
    plan_k<<<1, 512>>>();
    // weight transpose + split (independent of routing; order irrelevant)
    tsplit_k<<<dim3(HIDV / 32, DIMV / 32, NEXP), dim3(32, 8)>>>(w1, DIMV, HIDV, 0);
    tsplit_k<<<dim3(HIDV / 32, DIMV / 32, NEXP), dim3(32, 8)>>>(w2, DIMV, HIDV, 1);
    tsplit_k<<<dim3(DIMV / 32, HIDV / 32, NEXP), dim3(32, 8)>>>(w3, HIDV, DIMV, 2);
    gather_k<<<MAXROWS, 256>>>(x);
    gemm1_k<<<dim3(HIDV / BN, MAXTILE), 256, SM1>>>();
    gemm2_k<<<dim3(DIMV / BN, MAXTILE), 256, SM2>>>(out);
}

// round 4
// speedup vs baseline: 1.3716x; 1.3716x over previous
#include <cuda_runtime.h>
#include <cuda_bf16.h>
#include <cstdint>

typedef __nv_bfloat16 bf16;

// tcgen05 is only legal in an arch-specific (compute_103a) device pass.
#if defined(__CUDA_ARCH__) && (__CUDA_ARCH__ == 1030) && \
    (defined(__CUDA_ARCH_FEAT_SM103_ALL) || defined(__CUDA_ARCH_FEAT_SM100_ALL))
#define TC_OK 1
#else
#define TC_OK 0
#endif

#define DIMV 768
#define HIDV 2048
#define TOKV 4096
#define NEXP 8
#define MAXTILE 40
#define MAXROWS (MAXTILE*128)

#define BM 128
#define BN 64
#define KC 64          // tcgen05 stage K elems (128B row)
#define BK 32          // HMMA stage K elems
#define SROW 40        // HMMA smem row pitch (bf16)

// ------------------------- device scratch ---------------------------------
__device__ bf16 gW1h[(size_t)NEXP*HIDV*DIMV];
__device__ bf16 gW1l[(size_t)NEXP*HIDV*DIMV];
__device__ bf16 gW2h[(size_t)NEXP*HIDV*DIMV];
__device__ bf16 gW2l[(size_t)NEXP*HIDV*DIMV];
__device__ bf16 gW3h[(size_t)NEXP*DIMV*HIDV];
__device__ bf16 gW3l[(size_t)NEXP*DIMV*HIDV];
__device__ bf16 gXh[(size_t)MAXROWS*DIMV];
__device__ bf16 gXl[(size_t)MAXROWS*DIMV];
__device__ bf16 gUh[(size_t)MAXROWS*HIDV];
__device__ bf16 gUl[(size_t)MAXROWS*HIDV];
__device__ int   gTokE[TOKV];
__device__ float gP[TOKV];
__device__ int   gRowTok[MAXROWS];
__device__ int   gTileE[MAXTILE];

// ------------------------- common helpers ----------------------------------
__device__ __forceinline__ uint32_t smem_u32(const void* p) {
    uint32_t a;
    asm("{ .reg .u64 t; cvta.to.shared.u64 t, %1; cvt.u32.u64 %0, t; }" : "=r"(a) : "l"(p));
    return a;
}
__device__ __forceinline__ void cp16(uint32_t s, const void* g) {
    asm volatile("cp.async.cg.shared.global [%0], [%1], 16;\n" :: "r"(s), "l"(g));
}
__device__ __forceinline__ void cpcommit() { asm volatile("cp.async.commit_group;\n"); }
__device__ __forceinline__ void split2(float v, bf16& h, bf16& l) {
    h = __float2bfloat16(v);
    l = __float2bfloat16(v - __bfloat162float(h));
}
__device__ __forceinline__ void mma_bf16(float* c, const unsigned* a, const unsigned* b) {
    asm volatile(
        "mma.sync.aligned.m16n8k16.row.col.f32.bf16.bf16.f32 "
        "{%0,%1,%2,%3},{%4,%5,%6,%7},{%8,%9},{%0,%1,%2,%3};\n"
        : "+f"(c[0]), "+f"(c[1]), "+f"(c[2]), "+f"(c[3])
        : "r"(a[0]), "r"(a[1]), "r"(a[2]), "r"(a[3]), "r"(b[0]), "r"(b[1]));
}

#define SWZ(x) ((x) ^ (((x) >> 3) & 0x70))

// ------------------------- tcgen05 helpers (bodies arch-gated) -------------
__device__ __forceinline__ uint32_t elect1() {
    uint32_t p = 0;
#if TC_OK
    asm volatile("{ .reg .pred p; elect.sync _|p, 0xFFFFFFFF; selp.b32 %0,1,0,p; }" : "=r"(p));
#endif
    return p;
}
__device__ __forceinline__ uint64_t make_desc(uint32_t addr) {
    const uint64_t base = (uint64_t(2) << 61) | (uint64_t(1) << 46)
                        | (uint64_t(64) << 32) | (uint64_t(1) << 16);
    return base | ((uint64_t)(addr >> 4) & 0x3FFF);
}
#define IDESC 0x8100490u   // f16-kind, bf16 x bf16 -> f32, M=128, N=64

__device__ __forceinline__ void mma_ss(uint32_t d, uint64_t ad, uint64_t bd, uint32_t en) {
#if TC_OK
    asm volatile(
        "{\n .reg .pred p;\n setp.ne.u32 p, %4, 0;\n"
        " tcgen05.mma.cta_group::1.kind::f16 [%0], %1, %2, %3, {%5,%5,%5,%5}, p;\n}"
        :: "r"(d), "l"(ad), "l"(bd), "r"(IDESC), "r"(en), "r"(0u) : "memory");
#endif
}
__device__ __forceinline__ void mma_commit(uint32_t mbar) {
#if TC_OK
    asm volatile(
        "tcgen05.commit.cta_group::1.mbarrier::arrive::one.shared::cluster.b64 [%0];"
        :: "r"(mbar) : "memory");
#endif
}
__device__ __forceinline__ void mbar_init(uint32_t a, uint32_t c) {
#if TC_OK
    asm volatile("mbarrier.init.shared.b64 [%0], %1;" :: "r"(a), "r"(c) : "memory");
#endif
}
__device__ __forceinline__ void mbar_inval(uint32_t a) {
#if TC_OK
    asm volatile("mbarrier.inval.shared.b64 [%0];" :: "r"(a) : "memory");
#endif
}
__device__ __forceinline__ void mbar_wait(uint32_t a, uint32_t ph) {
#if TC_OK
    uint32_t ok = 0;
    while (!ok) {
        asm volatile(
            "{\n .reg .pred P;\n"
            " mbarrier.try_wait.parity.acquire.cta.shared::cta.b64 P, [%1], %2, 0x989680;\n"
            " selp.b32 %0, 1, 0, P;\n}"
            : "=r"(ok) : "r"(a), "r"(ph) : "memory");
    }
#endif
}
__device__ __forceinline__ void tmem_alloc(uint32_t smem_ptr, uint32_t ncols) {
#if TC_OK
    asm volatile("tcgen05.alloc.cta_group::1.sync.aligned.shared::cta.b32 [%0], %1;"
                 :: "r"(smem_ptr), "r"(ncols) : "memory");
#endif
}
__device__ __forceinline__ void tmem_dealloc(uint32_t tmem, uint32_t ncols) {
#if TC_OK
    asm volatile("tcgen05.relinquish_alloc_permit.cta_group::1.sync.aligned;");
    asm volatile("tcgen05.dealloc.cta_group::1.sync.aligned.b32 %0, %1;" :: "r"(tmem), "r"(ncols));
#endif
}
__device__ __forceinline__ void ldtm32(uint32_t* r, uint32_t ta) {
#if TC_OK
    asm volatile(
        "tcgen05.ld.sync.aligned.32x32b.x32.b32 "
        "{%0,%1,%2,%3,%4,%5,%6,%7,%8,%9,%10,%11,%12,%13,%14,%15,"
        "%16,%17,%18,%19,%20,%21,%22,%23,%24,%25,%26,%27,%28,%29,%30,%31}, [%32];"
        : "=r"(r[0]), "=r"(r[1]), "=r"(r[2]), "=r"(r[3]), "=r"(r[4]), "=r"(r[5]),
          "=r"(r[6]), "=r"(r[7]), "=r"(r[8]), "=r"(r[9]), "=r"(r[10]), "=r"(r[11]),
          "=r"(r[12]), "=r"(r[13]), "=r"(r[14]), "=r"(r[15]), "=r"(r[16]), "=r"(r[17]),
          "=r"(r[18]), "=r"(r[19]), "=r"(r[20]), "=r"(r[21]), "=r"(r[22]), "=r"(r[23]),
          "=r"(r[24]), "=r"(r[25]), "=r"(r[26]), "=r"(r[27]), "=r"(r[28]), "=r"(r[29]),
          "=r"(r[30]), "=r"(r[31])
        : "r"(ta));
#endif
}
__device__ __forceinline__ void tm_wait_ld() {
#if TC_OK
    asm volatile("tcgen05.wait::ld.sync.aligned;" ::: "memory");
#endif
}
__device__ __forceinline__ void tm_fence_after() {
#if TC_OK
    asm volatile("tcgen05.fence::after_thread_sync;" ::: "memory");
#endif
}
__device__ __forceinline__ void fence_async_smem() {
#if TC_OK
    asm volatile("fence.proxy.async.shared::cta;" ::: "memory");
#endif
}

// ------------------------- router ------------------------------------------
__global__ void router_k(const float* __restrict__ x,
                         const float* __restrict__ rw,
                         const float* __restrict__ rb) {
    int wid  = (blockIdx.x * blockDim.x + threadIdx.x) >> 5;
    int lane = threadIdx.x & 31;
    if (wid >= TOKV) return;
    const float* xr = x + (size_t)wid * DIMV;
    float acc[NEXP];
#pragma unroll
    for (int e = 0; e < NEXP; e++) acc[e] = 0.f;
    for (int k = lane; k < DIMV; k += 32) {
        float xv = xr[k];
        const float* w = rw + k * NEXP;
#pragma unroll
        for (int e = 0; e < NEXP; e++) acc[e] += xv * w[e];
    }
#pragma unroll
    for (int off = 16; off; off >>= 1)
#pragma unroll
        for (int e = 0; e < NEXP; e++)
            acc[e] += __shfl_xor_sync(0xffffffffu, acc[e], off);
    if (lane == 0) {
        float l[NEXP];
        float m = -1e30f; int mi = 0;
#pragma unroll
        for (int e = 0; e < NEXP; e++) {
            l[e] = acc[e] + rb[e];
            if (l[e] > m) { m = l[e]; mi = e; }
        }
        float s = 0.f;
#pragma unroll
        for (int e = 0; e < NEXP; e++) s += expf(l[e] - m);
        gTokE[wid] = mi;
        gP[wid] = 1.f / s;
    }
}

// ------------------------- plan (single block) ------------------------------
__global__ void plan_k() {
    __shared__ int cnt[NEXP], cur[NEXP], base[NEXP];
    int tid = threadIdx.x;
    if (tid < NEXP) { cnt[tid] = 0; cur[tid] = 0; }
    __syncthreads();
    for (int t = tid; t < TOKV; t += blockDim.x) atomicAdd(&cnt[gTokE[t]], 1);
    __syncthreads();
    if (tid == 0) {
        int acc = 0, tc = 0;
        for (int e = 0; e < NEXP; e++) {
            base[e] = acc;
            int nt = (cnt[e] + 127) >> 7;
            for (int i = 0; i < nt && tc < MAXTILE; i++) gTileE[tc++] = e;
            acc += nt * 128;
        }
        for (; tc < MAXTILE; tc++) gTileE[tc] = 0;
    }
    __syncthreads();
    for (int r = tid; r < MAXROWS; r += blockDim.x) gRowTok[r] = -1;
    __syncthreads();
    for (int t = tid; t < TOKV; t += blockDim.x) {
        int e = gTokE[t];
        int s = atomicAdd(&cur[e], 1);
        gRowTok[base[e] + s] = t;
    }
}

// ---------------- weight transpose + bf16 split ----------------------------
__global__ void tsplit_k(const float* __restrict__ src, int R, int C, int which) {
    __shared__ float tile[32][33];
    bf16 *dh, *dl;
    if (which == 0)      { dh = gW1h; dl = gW1l; }
    else if (which == 1) { dh = gW2h; dl = gW2l; }
    else                 { dh = gW3h; dl = gW3l; }
    int e = blockIdx.z;
    int c0 = blockIdx.x * 32, r0 = blockIdx.y * 32;
    int tx = threadIdx.x, ty = threadIdx.y;
    const float* s = src + (size_t)e * R * C;
#pragma unroll
    for (int i = 0; i < 4; i++) {
        int r = r0 + ty + i * 8;
        tile[ty + i * 8][tx] = s[(size_t)r * C + c0 + tx];
    }
    __syncthreads();
    bf16* dhp = dh + (size_t)e * C * R;
    bf16* dlp = dl + (size_t)e * C * R;
#pragma unroll
    for (int i = 0; i < 4; i++) {
        int c = c0 + ty + i * 8;
        int r = r0 + tx;
        float v = tile[tx][ty + i * 8];
        bf16 h, l; split2(v, h, l);
        dhp[(size_t)c * R + r] = h;
        dlp[(size_t)c * R + r] = l;
    }
}

// ------------------------- gather X + split --------------------------------
__global__ void gather_k(const float* __restrict__ x) {
    int row = blockIdx.x;
    int tok = gRowTok[row];
    for (int k = threadIdx.x; k < DIMV; k += blockDim.x) {
        float v = (tok >= 0) ? x[(size_t)tok * DIMV + k] : 0.f;
        bf16 h, l; split2(v, h, l);
        gXh[(size_t)row * DIMV + k] = h;
        gXl[(size_t)row * DIMV + k] = l;
    }
}

// ===================== tcgen05 GEMM path ===================================
#define G1_AH 1024
#define G1_AL 33792
#define G1_B1H 66560
#define G1_B1L 82944
#define G1_B2H 99328
#define G1_B2L 115712
#define G1_SMEM 132096
#define ABUF 16384
#define BBUF 8192

#if TC_OK
__device__ __forceinline__ void g1_fill(uint32_t sb, int buf, int kc,
                                        const bf16* gA_h, const bf16* gA_l,
                                        const bf16* s1h, const bf16* s1l,
                                        const bf16* s2h, const bf16* s2l, int tid) {
    uint32_t ah = sb + G1_AH + buf * ABUF;
    uint32_t al = sb + G1_AL + buf * ABUF;
#pragma unroll
    for (int i = 0; i < 4; i++) {
        int id = tid * 4 + i;
        int row = id >> 3, cb = id & 7;
        uint32_t off = SWZ(row * 128 + cb * 16);
        size_t go = (size_t)row * DIMV + kc + cb * 8;
        cp16(ah + off, gA_h + go);
        cp16(al + off, gA_l + go);
    }
    uint32_t b1h = sb + G1_B1H + buf * BBUF;
    uint32_t b1l = sb + G1_B1L + buf * BBUF;
    uint32_t b2h = sb + G1_B2H + buf * BBUF;
    uint32_t b2l = sb + G1_B2L + buf * BBUF;
#pragma unroll
    for (int i = 0; i < 2; i++) {
        int id = tid * 2 + i;
        int row = id >> 3, cb = id & 7;
        uint32_t off = SWZ(row * 128 + cb * 16);
        size_t go = (size_t)row * DIMV + kc + cb * 8;
        cp16(b1h + off, s1h + go);
        cp16(b1l + off, s1l + go);
        cp16(b2h + off, s2h + go);
        cp16(b2l + off, s2l + go);
    }
    cpcommit();
}
#endif

__global__ __launch_bounds__(256) void gemm1_tc() {
#if TC_OK
    extern __shared__ char smem[];
    uint32_t sb = smem_u32(smem);
    int tid = threadIdx.x, wid = tid >> 5, lane = tid & 31;
    int tile = blockIdx.y, nb0 = blockIdx.x * BN;
    int e = gTileE[tile];

    if (wid == 0) tmem_alloc(sb, 128);
    if (tid == 0) { mbar_init(sb + 8, 1); mbar_init(sb + 16, 1); }
    __syncthreads();
    uint32_t tmem;
    asm volatile("ld.shared.b32 %0, [%1];" : "=r"(tmem) : "r"(sb));

    const bf16* gA_h = gXh + (size_t)tile * BM * DIMV;
    const bf16* gA_l = gXl + (size_t)tile * BM * DIMV;
    const bf16* s1h = gW1h + ((size_t)e * HIDV + nb0) * DIMV;
    const bf16* s1l = gW1l + ((size_t)e * HIDV + nb0) * DIMV;
    const bf16* s2h = gW2h + ((size_t)e * HIDV + nb0) * DIMV;
    const bf16* s2l = gW2l + ((size_t)e * HIDV + nb0) * DIMV;

    const int NS = DIMV / KC;  // 12
    g1_fill(sb, 0, 0, gA_h, gA_l, s1h, s1l, s2h, s2l, tid);

    for (int s = 0; s < NS; s++) {
        if (s + 1 < NS) {
            int nb = (s + 1) & 1;
            if (s + 1 >= 2) mbar_wait(sb + 8 + nb * 8, (((s + 1) >> 1) - 1) & 1);
            g1_fill(sb, nb, (s + 1) * KC, gA_h, gA_l, s1h, s1l, s2h, s2l, tid);
            asm volatile("cp.async.wait_group 1;\n");
        } else {
            asm volatile("cp.async.wait_group 0;\n");
        }
        __syncthreads();
        if (wid == 0) {
            fence_async_smem();
            if (elect1()) {
                int buf = s & 1;
                uint64_t ad  = make_desc(sb + G1_AH  + buf * ABUF);
                uint64_t ald = make_desc(sb + G1_AL  + buf * ABUF);
                uint64_t b1h = make_desc(sb + G1_B1H + buf * BBUF);
                uint64_t b1l = make_desc(sb + G1_B1L + buf * BBUF);
                uint64_t b2h = make_desc(sb + G1_B2H + buf * BBUF);
                uint64_t b2l = make_desc(sb + G1_B2L + buf * BBUF);
#pragma unroll
                for (int k = 0; k < 4; k++) {
                    uint32_t en = (s == 0 && k == 0) ? 0u : 1u;
                    mma_ss(tmem,      ad  + k * 2, b1h + k * 2, en);
                    mma_ss(tmem,      ad  + k * 2, b1l + k * 2, 1u);
                    mma_ss(tmem,      ald + k * 2, b1h + k * 2, 1u);
                    mma_ss(tmem + 64, ad  + k * 2, b2h + k * 2, en);
                    mma_ss(tmem + 64, ad  + k * 2, b2l + k * 2, 1u);
                    mma_ss(tmem + 64, ald + k * 2, b2h + k * 2, 1u);
                }
                mma_commit(sb + 8 + (s & 1) * 8);
            }
        }
    }

    mbar_wait(sb + 8 + ((NS - 1) & 1) * 8, ((NS - 1) >> 1) & 1);
    tm_fence_after();

    if (wid < 4) {
        int grow = tile * 128 + wid * 32 + lane;
        bf16* dh = gUh + (size_t)grow * HIDV + nb0;
        bf16* dl = gUl + (size_t)grow * HIDV + nb0;
#pragma unroll
        for (int half = 0; half < 2; half++) {
            uint32_t r1[32], r2[32];
            ldtm32(r1, tmem + half * 32);
            ldtm32(r2, tmem + 64 + half * 32);
            tm_wait_ld();
#pragma unroll
            for (int j = 0; j < 32; j += 2) {
                float h1a = __uint_as_float(r1[j]),     h2a = __uint_as_float(r2[j]);
                float h1b = __uint_as_float(r1[j + 1]), h2b = __uint_as_float(r2[j + 1]);
                float ua = h1a * (1.f / (1.f + expf(-h1a))) * h2a;
                float ub = h1b * (1.f / (1.f + expf(-h1b))) * h2b;
                bf16 ha, la, hb, lb;
                split2(ua, ha, la);
                split2(ub, hb, lb);
                __nv_bfloat162 vh; vh.x = ha; vh.y = hb;
                __nv_bfloat162 vl; vl.x = la; vl.y = lb;
                *(__nv_bfloat162*)(dh + half * 32 + j) = vh;
                *(__nv_bfloat162*)(dl + half * 32 + j) = vl;
            }
        }
    }
    __syncthreads();
    if (tid == 0) { mbar_inval(sb + 8); mbar_inval(sb + 16); }
    __syncthreads();
    if (wid == 0) tmem_dealloc(tmem, 128);
#endif
}

#define G2_AH 1024
#define G2_AL 33792
#define G2_BH 66560
#define G2_BL 82944
#define G2_SMEM 99328

#if TC_OK
__device__ __forceinline__ void g2_fill(uint32_t sb, int buf, int kc,
                                        const bf16* gA_h, const bf16* gA_l,
                                        const bf16* sbh, const bf16* sbl, int tid) {
    uint32_t ah = sb + G2_AH + buf * ABUF;
    uint32_t al = sb + G2_AL + buf * ABUF;
#pragma unroll
    for (int i = 0; i < 4; i++) {
        int id = tid * 4 + i;
        int row = id >> 3, cb = id & 7;
        uint32_t off = SWZ(row * 128 + cb * 16);
        size_t go = (size_t)row * HIDV + kc + cb * 8;
        cp16(ah + off, gA_h + go);
        cp16(al + off, gA_l + go);
    }
    uint32_t bh = sb + G2_BH + buf * BBUF;
    uint32_t bl = sb + G2_BL + buf * BBUF;
#pragma unroll
    for (int i = 0; i < 2; i++) {
        int id = tid * 2 + i;
        int row = id >> 3, cb = id & 7;
        uint32_t off = SWZ(row * 128 + cb * 16);
        size_t go = (size_t)row * HIDV + kc + cb * 8;
        cp16(bh + off, sbh + go);
        cp16(bl + off, sbl + go);
    }
    cpcommit();
}
#endif

__global__ __launch_bounds__(256) void gemm2_tc(float* __restrict__ out) {
#if TC_OK
    extern __shared__ char smem[];
    uint32_t sb = smem_u32(smem);
    int tid = threadIdx.x, wid = tid >> 5, lane = tid & 31;
    int tile = blockIdx.y, nb0 = blockIdx.x * BN;
    int e = gTileE[tile];

    if (wid == 0) tmem_alloc(sb, 128);
    if (tid == 0) { mbar_init(sb + 8, 1); mbar_init(sb + 16, 1); }
    __syncthreads();
    uint32_t tmem;
    asm volatile("ld.shared.b32 %0, [%1];" : "=r"(tmem) : "r"(sb));

    const bf16* gA_h = gUh + (size_t)tile * BM * HIDV;
    const bf16* gA_l = gUl + (size_t)tile * BM * HIDV;
    const bf16* sbh = gW3h + ((size_t)e * DIMV + nb0) * HIDV;
    const bf16* sbl = gW3l + ((size_t)e * DIMV + nb0) * HIDV;

    const int NS = HIDV / KC;  // 32
    g2_fill(sb, 0, 0, gA_h, gA_l, sbh, sbl, tid);

    for (int s = 0; s < NS; s++) {
        if (s + 1 < NS) {
            int nb = (s + 1) & 1;
            if (s + 1 >= 2) mbar_wait(sb + 8 + nb * 8, (((s + 1) >> 1) - 1) & 1);
            g2_fill(sb, nb, (s + 1) * KC, gA_h, gA_l, sbh, sbl, tid);
            asm volatile("cp.async.wait_group 1;\n");
        } else {
            asm volatile("cp.async.wait_group 0;\n");
        }
        __syncthreads();
        if (wid == 0) {
            fence_async_smem();
            if (elect1()) {
                int buf = s & 1;
                uint64_t ad  = make_desc(sb + G2_AH + buf * ABUF);
                uint64_t ald = make_desc(sb + G2_AL + buf * ABUF);
                uint64_t bh  = make_desc(sb + G2_BH + buf * BBUF);
                uint64_t bl  = make_desc(sb + G2_BL + buf * BBUF);
#pragma unroll
                for (int k = 0; k < 4; k++) {
                    uint32_t en = (s == 0 && k == 0) ? 0u : 1u;
                    mma_ss(tmem, ad  + k * 2, bh + k * 2, en);
                    mma_ss(tmem, ad  + k * 2, bl + k * 2, 1u);
                    mma_ss(tmem, ald + k * 2, bh + k * 2, 1u);
                }
                mma_commit(sb + 8 + (s & 1) * 8);
            }
        }
    }

    mbar_wait(sb + 8 + ((NS - 1) & 1) * 8, ((NS - 1) >> 1) & 1);
    tm_fence_after();

    if (wid < 4) {
        int grow = tile * 128 + wid * 32 + lane;
        int tok = gRowTok[grow];
        float p = (tok >= 0) ? gP[tok] : 0.f;
        uint32_t r1[32], r2[32];
        ldtm32(r1, tmem);
        ldtm32(r2, tmem + 32);
        tm_wait_ld();
        if (tok >= 0) {
            float* o = out + (size_t)tok * DIMV + nb0;
#pragma unroll
            for (int j = 0; j < 32; j++) {
                o[j]      = __bfloat162float(__float2bfloat16(__uint_as_float(r1[j]))) * p;
                o[32 + j] = __bfloat162float(__float2bfloat16(__uint_as_float(r2[j]))) * p;
            }
        }
    }
    __syncthreads();
    if (tid == 0) { mbar_inval(sb + 8); mbar_inval(sb + 16); }
    __syncthreads();
    if (wid == 0) tmem_dealloc(tmem, 128);
#endif
}

// ===================== HMMA fallback path ==================================
#if !TC_OK && defined(__CUDA_ARCH__)
#define HM_OK 1
#else
#define HM_OK 0
#endif

#if HM_OK
__device__ __forceinline__ void h1_load(
    bf16* a_h, bf16* a_l, bf16* b1h, bf16* b1l, bf16* b2h, bf16* b2l,
    const bf16* gAh, const bf16* gAl,
    const bf16* gB1h, const bf16* gB1l, const bf16* gB2h, const bf16* gB2l,
    int kc, int tid)
{
#pragma unroll
    for (int i = 0; i < 2; i++) {
        int q = tid * 2 + i, r = q >> 2, ko = (q & 3) * 8;
        size_t go = (size_t)r * DIMV + kc + ko;
        uint32_t so = smem_u32(a_h + r * SROW + ko);
        cp16(so, gAh + go);
        cp16(smem_u32(a_l + r * SROW + ko), gAl + go);
    }
    {
        int r = tid >> 2, ko = (tid & 3) * 8;
        size_t go = (size_t)r * DIMV + kc + ko;
        cp16(smem_u32(b1h + r * SROW + ko), gB1h + go);
        cp16(smem_u32(b1l + r * SROW + ko), gB1l + go);
        cp16(smem_u32(b2h + r * SROW + ko), gB2h + go);
        cp16(smem_u32(b2l + r * SROW + ko), gB2l + go);
    }
    cpcommit();
}
#endif

__global__ __launch_bounds__(256, 1) void gemm1_hm() {
#if HM_OK
    extern __shared__ bf16 smh[];
    bf16* Ah  = smh;
    bf16* Al  = Ah  + 2 * BM * SROW;
    bf16* B1h = Al  + 2 * BM * SROW;
    bf16* B1l = B1h + 2 * BN * SROW;
    bf16* B2h = B1l + 2 * BN * SROW;
    bf16* B2l = B2h + 2 * BN * SROW;

    int tile = blockIdx.y, nb0 = blockIdx.x * BN;
    int e = gTileE[tile];
    int tid = threadIdx.x, lane = tid & 31, warp = tid >> 5;
    int wm = warp & 3, wn = warp >> 2;
    int g = lane >> 2, t4 = lane & 3;

    const bf16* gAh  = gXh + (size_t)tile * BM * DIMV;
    const bf16* gAl  = gXl + (size_t)tile * BM * DIMV;
    const bf16* gB1h = gW1h + ((size_t)e * HIDV + nb0) * DIMV;
    const bf16* gB1l = gW1l + ((size_t)e * HIDV + nb0) * DIMV;
    const bf16* gB2h = gW2h + ((size_t)e * HIDV + nb0) * DIMV;
    const bf16* gB2l = gW2l + ((size_t)e * HIDV + nb0) * DIMV;

    float acc1[2][4][4], acc2[2][4][4];
#pragma unroll
    for (int m = 0; m < 2; m++)
#pragma unroll
        for (int n = 0; n < 4; n++)
#pragma unroll
            for (int i = 0; i < 4; i++) { acc1[m][n][i] = 0.f; acc2[m][n][i] = 0.f; }

    const int NSTEP = DIMV / BK;
    h1_load(Ah, Al, B1h, B1l, B2h, B2l, gAh, gAl, gB1h, gB1l, gB2h, gB2l, 0, tid);

    for (int s = 0; s < NSTEP; s++) {
        if (s + 1 < NSTEP) {
            int buf = (s + 1) & 1;
            h1_load(Ah + buf * BM * SROW, Al + buf * BM * SROW,
                    B1h + buf * BN * SROW, B1l + buf * BN * SROW,
                    B2h + buf * BN * SROW, B2l + buf * BN * SROW,
                    gAh, gAl, gB1h, gB1l, gB2h, gB2l, (s + 1) * BK, tid);
            asm volatile("cp.async.wait_group 1;\n");
        } else {
            asm volatile("cp.async.wait_group 0;\n");
        }
        __syncthreads();
        int buf = s & 1;
        const bf16* a_h = Ah  + buf * BM * SROW;
        const bf16* a_l = Al  + buf * BM * SROW;
        const bf16* b1h = B1h + buf * BN * SROW;
        const bf16* b1l = B1l + buf * BN * SROW;
        const bf16* b2h = B2h + buf * BN * SROW;
        const bf16* b2l = B2l + buf * BN * SROW;

#pragma unroll
        for (int kk = 0; kk < 2; kk++) {
            int kb = kk * 16;
            unsigned Afh[2][4], Afl[2][4];
#pragma unroll
            for (int mt = 0; mt < 2; mt++) {
                int rb = wm * 32 + mt * 16 + g;
                const bf16* p = a_h + rb * SROW + kb + t4 * 2;
                Afh[mt][0] = *(const unsigned*)(p);
                Afh[mt][1] = *(const unsigned*)(p + 8 * SROW);
                Afh[mt][2] = *(const unsigned*)(p + 8);
                Afh[mt][3] = *(const unsigned*)(p + 8 * SROW + 8);
                const bf16* q = a_l + rb * SROW + kb + t4 * 2;
                Afl[mt][0] = *(const unsigned*)(q);
                Afl[mt][1] = *(const unsigned*)(q + 8 * SROW);
                Afl[mt][2] = *(const unsigned*)(q + 8);
                Afl[mt][3] = *(const unsigned*)(q + 8 * SROW + 8);
            }
            {
                unsigned Bh[4][2], Bl[4][2];
#pragma unroll
                for (int nt = 0; nt < 4; nt++) {
                    int nr = wn * 32 + nt * 8 + g;
                    const bf16* p = b1h + nr * SROW + kb + t4 * 2;
                    Bh[nt][0] = *(const unsigned*)(p);
                    Bh[nt][1] = *(const unsigned*)(p + 8);
                    const bf16* q = b1l + nr * SROW + kb + t4 * 2;
                    Bl[nt][0] = *(const unsigned*)(q);
                    Bl[nt][1] = *(const unsigned*)(q + 8);
                }
#pragma unroll
                for (int mt = 0; mt < 2; mt++)
#pragma unroll
                    for (int nt = 0; nt < 4; nt++) {
                        mma_bf16(acc1[mt][nt], Afh[mt], Bh[nt]);
                        mma_bf16(acc1[mt][nt], Afh[mt], Bl[nt]);
                        mma_bf16(acc1[mt][nt], Afl[mt], Bh[nt]);
                    }
            }
            {
                unsigned Bh[4][2], Bl[4][2];
#pragma unroll
                for (int nt = 0; nt < 4; nt++) {
                    int nr = wn * 32 + nt * 8 + g;
                    const bf16* p = b2h + nr * SROW + kb + t4 * 2;
                    Bh[nt][0] = *(const unsigned*)(p);
                    Bh[nt][1] = *(const unsigned*)(p + 8);
                    const bf16* q = b2l + nr * SROW + kb + t4 * 2;
                    Bl[nt][0] = *(const unsigned*)(q);
                    Bl[nt][1] = *(const unsigned*)(q + 8);
                }
#pragma unroll
                for (int mt = 0; mt < 2; mt++)
#pragma unroll
                    for (int nt = 0; nt < 4; nt++) {
                        mma_bf16(acc2[mt][nt], Afh[mt], Bh[nt]);
                        mma_bf16(acc2[mt][nt], Afh[mt], Bl[nt]);
                        mma_bf16(acc2[mt][nt], Afl[mt], Bh[nt]);
                    }
            }
        }
        __syncthreads();
    }

#pragma unroll
    for (int mt = 0; mt < 2; mt++) {
#pragma unroll
        for (int nt = 0; nt < 4; nt++) {
            int lr = wm * 32 + mt * 16 + g;
            int grow = tile * 128 + lr;
            int col = nb0 + wn * 32 + nt * 8 + t4 * 2;
            const float* c1 = acc1[mt][nt];
            const float* c2 = acc2[mt][nt];
#pragma unroll
            for (int half = 0; half < 2; half++) {
                int r = grow + half * 8;
                float h1a = c1[half * 2 + 0], h1b = c1[half * 2 + 1];
                float h2a = c2[half * 2 + 0], h2b = c2[half * 2 + 1];
                float ua = h1a * (1.f / (1.f + expf(-h1a))) * h2a;
                float ub = h1b * (1.f / (1.f + expf(-h1b))) * h2b;
                bf16 ha, la, hb, lb;
                split2(ua, ha, la);
                split2(ub, hb, lb);
                __nv_bfloat162 vh; vh.x = ha; vh.y = hb;
                __nv_bfloat162 vl; vl.x = la; vl.y = lb;
                *(__nv_bfloat162*)(gUh + (size_t)r * HIDV + col) = vh;
                *(__nv_bfloat162*)(gUl + (size_t)r * HIDV + col) = vl;
            }
        }
    }
#endif
}

#if HM_OK
__device__ __forceinline__ void h2_load(
    bf16* a_h, bf16* a_l, bf16* bh, bf16* bl,
    const bf16* gAh, const bf16* gAl, const bf16* gBh, const bf16* gBl,
    int kc, int tid)
{
#pragma unroll
    for (int i = 0; i < 2; i++) {
        int q = tid * 2 + i, r = q >> 2, ko = (q & 3) * 8;
        size_t go = (size_t)r * HIDV + kc + ko;
        cp16(smem_u32(a_h + r * SROW + ko), gAh + go);
        cp16(smem_u32(a_l + r * SROW + ko), gAl + go);
    }
    {
        int r = tid >> 2, ko = (tid & 3) * 8;
        size_t go = (size_t)r * HIDV + kc + ko;
        cp16(smem_u32(bh + r * SROW + ko), gBh + go);
        cp16(smem_u32(bl + r * SROW + ko), gBl + go);
    }
    cpcommit();
}
#endif

__global__ __launch_bounds__(256, 1) void gemm2_hm(float* __restrict__ out) {
#if HM_OK
    extern __shared__ bf16 smh[];
    bf16* Ah = smh;
    bf16* Al = Ah + 2 * BM * SROW;
    bf16* Bh = Al + 2 * BM * SROW;
    bf16* Bl = Bh + 2 * BN * SROW;

    int tile = blockIdx.y, nb0 = blockIdx.x * BN;
    int e = gTileE[tile];
    int tid = threadIdx.x, lane = tid & 31, warp = tid >> 5;
    int wm = warp & 3, wn = warp >> 2;
    int g = lane >> 2, t4 = lane & 3;

    const bf16* gAh2 = gUh + (size_t)tile * BM * HIDV;
    const bf16* gAl2 = gUl + (size_t)tile * BM * HIDV;
    const bf16* gBh2 = gW3h + ((size_t)e * DIMV + nb0) * HIDV;
    const bf16* gBl2 = gW3l + ((size_t)e * DIMV + nb0) * HIDV;

    float acc[2][4][4];
#pragma unroll
    for (int m = 0; m < 2; m++)
#pragma unroll
        for (int n = 0; n < 4; n++)
#pragma unroll
            for (int i = 0; i < 4; i++) acc[m][n][i] = 0.f;

    const int NSTEP = HIDV / BK;
    h2_load(Ah, Al, Bh, Bl, gAh2, gAl2, gBh2, gBl2, 0, tid);

    for (int s = 0; s < NSTEP; s++) {
        if (s + 1 < NSTEP) {
            int buf = (s + 1) & 1;
            h2_load(Ah + buf * BM * SROW, Al + buf * BM * SROW,
                    Bh + buf * BN * SROW, Bl + buf * BN * SROW,
                    gAh2, gAl2, gBh2, gBl2, (s + 1) * BK, tid);
            asm volatile("cp.async.wait_group 1;\n");
        } else {
            asm volatile("cp.async.wait_group 0;\n");
        }
        __syncthreads();
        int buf = s & 1;
        const bf16* a_h = Ah + buf * BM * SROW;
        const bf16* a_l = Al + buf * BM * SROW;
        const bf16* b_h = Bh + buf * BN * SROW;
        const bf16* b_l = Bl + buf * BN * SROW;

#pragma unroll
        for (int kk = 0; kk < 2; kk++) {
            int kb = kk * 16;
            unsigned Afh[2][4], Afl[2][4];
#pragma unroll
            for (int mt = 0; mt < 2; mt++) {
                int rb = wm * 32 + mt * 16 + g;
                const bf16* p = a_h + rb * SROW + kb + t4 * 2;
                Afh[mt][0] = *(const unsigned*)(p);
                Afh[mt][1] = *(const unsigned*)(p + 8 * SROW);
                Afh[mt][2] = *(const unsigned*)(p + 8);
                Afh[mt][3] = *(const unsigned*)(p + 8 * SROW + 8);
                const bf16* q = a_l + rb * SROW + kb + t4 * 2;
                Afl[mt][0] = *(const unsigned*)(q);
                Afl[mt][1] = *(const unsigned*)(q + 8 * SROW);
                Afl[mt][2] = *(const unsigned*)(q + 8);
                Afl[mt][3] = *(const unsigned*)(q + 8 * SROW + 8);
            }
            unsigned Bfh[4][2], Bfl[4][2];
#pragma unroll
            for (int nt = 0; nt < 4; nt++) {
                int nr = wn * 32 + nt * 8 + g;
                const bf16* p = b_h + nr * SROW + kb + t4 * 2;
                Bfh[nt][0] = *(const unsigned*)(p);
                Bfh[nt][1] = *(const unsigned*)(p + 8);
                const bf16* q = b_l + nr * SROW + kb + t4 * 2;
                Bfl[nt][0] = *(const unsigned*)(q);
                Bfl[nt][1] = *(const unsigned*)(q + 8);
            }
#pragma unroll
            for (int mt = 0; mt < 2; mt++)
#pragma unroll
                for (int nt = 0; nt < 4; nt++) {
                    mma_bf16(acc[mt][nt], Afh[mt], Bfh[nt]);
                    mma_bf16(acc[mt][nt], Afh[mt], Bfl[nt]);
                    mma_bf16(acc[mt][nt], Afl[mt], Bfh[nt]);
                }
        }
        __syncthreads();
    }

#pragma unroll
    for (int mt = 0; mt < 2; mt++) {
        int lr = wm * 32 + mt * 16 + g;
        int grow = tile * 128 + lr;
        int tokA = gRowTok[grow];
        int tokB = gRowTok[grow + 8];
        float pA = (tokA >= 0) ? gP[tokA] : 0.f;
        float pB = (tokB >= 0) ? gP[tokB] : 0.f;
#pragma unroll
        for (int nt = 0; nt < 4; nt++) {
            int col = nb0 + wn * 32 + nt * 8 + t4 * 2;
            const float* c = acc[mt][nt];
            if (tokA >= 0) {
                out[(size_t)tokA * DIMV + col]     = __bfloat162float(__float2bfloat16(c[0])) * pA;
                out[(size_t)tokA * DIMV + col + 1] = __bfloat162float(__float2bfloat16(c[1])) * pA;
            }
            if (tokB >= 0) {
                out[(size_t)tokB * DIMV + col]     = __bfloat162float(__float2bfloat16(c[2])) * pB;
                out[(size_t)tokB * DIMV + col + 1] = __bfloat162float(__float2bfloat16(c[3])) * pB;
            }
        }
    }
#endif
}

// ------------------------- launcher ----------------------------------------
extern "C" void kernel_launch(void* const* d_in, const int* in_sizes, int n_in,
                              void* d_out, int out_size) {
    const float* x  = (const float*)d_in[0];
    const float* rw = (const float*)d_in[1];
    const float* rb = (const float*)d_in[2];
    const float* w1 = (const float*)d_in[3];
    const float* w2 = (const float*)d_in[4];
    const float* w3 = (const float*)d_in[5];
    float* out = (float*)d_out;

    const int SH1 = (int)((2 * BM * SROW * 2 + 2 * BN * SROW * 4) * sizeof(bf16));
    const int SH2 = (int)((2 * BM * SROW * 2 + 2 * BN * SROW * 2) * sizeof(bf16));
    cudaFuncSetAttribute(gemm1_tc, cudaFuncAttributeMaxDynamicSharedMemorySize, G1_SMEM);
    cudaFuncSetAttribute(gemm2_tc, cudaFuncAttributeMaxDynamicSharedMemorySize, G2_SMEM);
    cudaFuncSetAttribute(gemm1_hm, cudaFuncAttributeMaxDynamicSharedMemorySize, SH1);
    cudaFuncSetAttribute(gemm2_hm, cudaFuncAttributeMaxDynamicSharedMemorySize, SH2);

    router_k<<<TOKV / 8, 256>>>(x, rw, rb);
    plan_k<<<1, 512>>>();
    tsplit_k<<<dim3(HIDV / 32, DIMV / 32, NEXP), dim3(32, 8)>>>(w1, DIMV, HIDV, 0);
    tsplit_k<<<dim3(HIDV / 32, DIMV / 32, NEXP), dim3(32, 8)>>>(w2, DIMV, HIDV, 1);
    tsplit_k<<<dim3(DIMV / 32, HIDV / 32, NEXP), dim3(32, 8)>>>(w3, HIDV, DIMV, 2);
    gather_k<<<MAXROWS, 256>>>(x);
    gemm1_tc<<<dim3(HIDV / BN, MAXTILE), 256, G1_SMEM>>>();
    gemm1_hm<<<dim3(HIDV / BN, MAXTILE), 256, SH1>>>();
    gemm2_tc<<<dim3(DIMV / BN, MAXTILE), 256, G2_SMEM>>>(out);
    gemm2_hm<<<dim3(DIMV / BN, MAXTILE), 256, SH2>>>(out);
}

// round 5
// speedup vs baseline: 1.7858x; 1.3020x over previous
#include <cuda_runtime.h>
#include <cuda_bf16.h>
#include <cstdint>

typedef __nv_bfloat16 bf16;

// tcgen05 is only legal in an arch-specific (compute_103a) device pass.
#if defined(__CUDA_ARCH__) && (__CUDA_ARCH__ == 1030) && \
    (defined(__CUDA_ARCH_FEAT_SM103_ALL) || defined(__CUDA_ARCH_FEAT_SM100_ALL))
#define TC_OK 1
#else
#define TC_OK 0
#endif

#define DIMV 768
#define HIDV 2048
#define TOKV 4096
#define NEXP 8
#define MAXGRP 24            // 256-row expert groups
#define NTILE (MAXGRP*2)     // 128-row tiles (HM path)
#define MAXROWS (MAXGRP*256) // 6144

#define BM 128
#define KC 32           // tcgen05 stage K elems (64B rows, SW64)
#define BK 32           // HMMA stage K elems
#define SROW 40         // HMMA smem row pitch (bf16)

// ------------------------- device scratch ---------------------------------
__device__ bf16 gW1h[(size_t)NEXP*HIDV*DIMV];
__device__ bf16 gW1l[(size_t)NEXP*HIDV*DIMV];
__device__ bf16 gW2h[(size_t)NEXP*HIDV*DIMV];
__device__ bf16 gW2l[(size_t)NEXP*HIDV*DIMV];
__device__ bf16 gW3h[(size_t)NEXP*DIMV*HIDV];
__device__ bf16 gW3l[(size_t)NEXP*DIMV*HIDV];
__device__ bf16 gXh[(size_t)MAXROWS*DIMV];
__device__ bf16 gXl[(size_t)MAXROWS*DIMV];
__device__ bf16 gUh[(size_t)MAXROWS*HIDV];
__device__ bf16 gUl[(size_t)MAXROWS*HIDV];
__device__ int   gTokE[TOKV];
__device__ float gP[TOKV];
__device__ int   gRowTok[MAXROWS];
__device__ int   gGrpE[MAXGRP];

// ------------------------- common helpers ----------------------------------
__device__ __forceinline__ uint32_t smem_u32(const void* p) {
    uint32_t a;
    asm("{ .reg .u64 t; cvta.to.shared.u64 t, %1; cvt.u32.u64 %0, t; }" : "=r"(a) : "l"(p));
    return a;
}
__device__ __forceinline__ void cp16(uint32_t s, const void* g) {
    asm volatile("cp.async.cg.shared.global [%0], [%1], 16;\n" :: "r"(s), "l"(g));
}
__device__ __forceinline__ void cpcommit() { asm volatile("cp.async.commit_group;\n"); }
__device__ __forceinline__ void split2(float v, bf16& h, bf16& l) {
    h = __float2bfloat16(v);
    l = __float2bfloat16(v - __bfloat162float(h));
}
__device__ __forceinline__ void mma_bf16(float* c, const unsigned* a, const unsigned* b) {
    asm volatile(
        "mma.sync.aligned.m16n8k16.row.col.f32.bf16.bf16.f32 "
        "{%0,%1,%2,%3},{%4,%5,%6,%7},{%8,%9},{%0,%1,%2,%3};\n"
        : "+f"(c[0]), "+f"(c[1]), "+f"(c[2]), "+f"(c[3])
        : "r"(a[0]), "r"(a[1]), "r"(a[2]), "r"(a[3]), "r"(b[0]), "r"(b[1]));
}

#define SWZ64(x) ((x) ^ (((x) >> 3) & 0x30))

// ------------------------- tcgen05 helpers (bodies arch-gated) -------------
__device__ __forceinline__ uint32_t elect1() {
    uint32_t p = 0;
#if TC_OK
    asm volatile("{ .reg .pred p; elect.sync _|p, 0xFFFFFFFF; selp.b32 %0,1,0,p; }" : "=r"(p));
#endif
    return p;
}
__device__ __forceinline__ uint64_t desc64(uint32_t addr) {
    // SW64 layout: layout_type=4, version=1 (Blackwell), SBO=32 (512B), LBO=1 (16B)
    const uint64_t base = (uint64_t(4) << 61) | (uint64_t(1) << 46)
                        | (uint64_t(32) << 32) | (uint64_t(1) << 16);
    return base | ((uint64_t)(addr >> 4) & 0x3FFF);
}
// kind::f16 idesc: dtype=F32(1<<4), atype=BF16(1<<7), btype=BF16(1<<10),
// N/8<<17, M/16<<24.  M=128, N=128 -> 0x8200490
#define IDESC 0x8200490u

__device__ __forceinline__ void mma_ss(uint32_t d, uint64_t ad, uint64_t bd, uint32_t en) {
#if TC_OK
    asm volatile(
        "{\n .reg .pred p;\n setp.ne.u32 p, %4, 0;\n"
        " tcgen05.mma.cta_group::1.kind::f16 [%0], %1, %2, %3, {%5,%5,%5,%5}, p;\n}"
        :: "r"(d), "l"(ad), "l"(bd), "r"(IDESC), "r"(en), "r"(0u) : "memory");
#endif
}
__device__ __forceinline__ void mma_commit(uint32_t mbar) {
#if TC_OK
    asm volatile(
        "tcgen05.commit.cta_group::1.mbarrier::arrive::one.shared::cluster.b64 [%0];"
        :: "r"(mbar) : "memory");
#endif
}
__device__ __forceinline__ void mbar_init(uint32_t a, uint32_t c) {
#if TC_OK
    asm volatile("mbarrier.init.shared.b64 [%0], %1;" :: "r"(a), "r"(c) : "memory");
#endif
}
__device__ __forceinline__ void mbar_inval(uint32_t a) {
#if TC_OK
    asm volatile("mbarrier.inval.shared.b64 [%0];" :: "r"(a) : "memory");
#endif
}
__device__ __forceinline__ void mbar_wait(uint32_t a, uint32_t ph) {
#if TC_OK
    uint32_t ok = 0;
    while (!ok) {
        asm volatile(
            "{\n .reg .pred P;\n"
            " mbarrier.try_wait.parity.acquire.cta.shared::cta.b64 P, [%1], %2, 0x989680;\n"
            " selp.b32 %0, 1, 0, P;\n}"
            : "=r"(ok) : "r"(a), "r"(ph) : "memory");
    }
#endif
}
__device__ __forceinline__ void tmem_alloc(uint32_t smem_ptr, uint32_t ncols) {
#if TC_OK
    asm volatile("tcgen05.alloc.cta_group::1.sync.aligned.shared::cta.b32 [%0], %1;"
                 :: "r"(smem_ptr), "r"(ncols) : "memory");
#endif
}
__device__ __forceinline__ void tmem_dealloc(uint32_t tmem, uint32_t ncols) {
#if TC_OK
    asm volatile("tcgen05.relinquish_alloc_permit.cta_group::1.sync.aligned;");
    asm volatile("tcgen05.dealloc.cta_group::1.sync.aligned.b32 %0, %1;" :: "r"(tmem), "r"(ncols));
#endif
}
__device__ __forceinline__ void ldtm32(uint32_t* r, uint32_t ta) {
#if TC_OK
    asm volatile(
        "tcgen05.ld.sync.aligned.32x32b.x32.b32 "
        "{%0,%1,%2,%3,%4,%5,%6,%7,%8,%9,%10,%11,%12,%13,%14,%15,"
        "%16,%17,%18,%19,%20,%21,%22,%23,%24,%25,%26,%27,%28,%29,%30,%31}, [%32];"
        : "=r"(r[0]), "=r"(r[1]), "=r"(r[2]), "=r"(r[3]), "=r"(r[4]), "=r"(r[5]),
          "=r"(r[6]), "=r"(r[7]), "=r"(r[8]), "=r"(r[9]), "=r"(r[10]), "=r"(r[11]),
          "=r"(r[12]), "=r"(r[13]), "=r"(r[14]), "=r"(r[15]), "=r"(r[16]), "=r"(r[17]),
          "=r"(r[18]), "=r"(r[19]), "=r"(r[20]), "=r"(r[21]), "=r"(r[22]), "=r"(r[23]),
          "=r"(r[24]), "=r"(r[25]), "=r"(r[26]), "=r"(r[27]), "=r"(r[28]), "=r"(r[29]),
          "=r"(r[30]), "=r"(r[31])
        : "r"(ta));
#endif
}
__device__ __forceinline__ void tm_wait_ld() {
#if TC_OK
    asm volatile("tcgen05.wait::ld.sync.aligned;" ::: "memory");
#endif
}
__device__ __forceinline__ void tm_fence_after() {
#if TC_OK
    asm volatile("tcgen05.fence::after_thread_sync;" ::: "memory");
#endif
}
__device__ __forceinline__ void fence_async_smem() {
#if TC_OK
    asm volatile("fence.proxy.async.shared::cta;" ::: "memory");
#endif
}

// ------------------------- router ------------------------------------------
__global__ void router_k(const float* __restrict__ x,
                         const float* __restrict__ rw,
                         const float* __restrict__ rb) {
    int wid  = (blockIdx.x * blockDim.x + threadIdx.x) >> 5;
    int lane = threadIdx.x & 31;
    if (wid >= TOKV) return;
    const float* xr = x + (size_t)wid * DIMV;
    float acc[NEXP];
#pragma unroll
    for (int e = 0; e < NEXP; e++) acc[e] = 0.f;
    for (int k = lane; k < DIMV; k += 32) {
        float xv = xr[k];
        const float* w = rw + k * NEXP;
#pragma unroll
        for (int e = 0; e < NEXP; e++) acc[e] += xv * w[e];
    }
#pragma unroll
    for (int off = 16; off; off >>= 1)
#pragma unroll
        for (int e = 0; e < NEXP; e++)
            acc[e] += __shfl_xor_sync(0xffffffffu, acc[e], off);
    if (lane == 0) {
        float l[NEXP];
        float m = -1e30f; int mi = 0;
#pragma unroll
        for (int e = 0; e < NEXP; e++) {
            l[e] = acc[e] + rb[e];
            if (l[e] > m) { m = l[e]; mi = e; }
        }
        float s = 0.f;
#pragma unroll
        for (int e = 0; e < NEXP; e++) s += expf(l[e] - m);
        gTokE[wid] = mi;
        gP[wid] = 1.f / s;
    }
}

// ------------------------- plan: 256-row expert groups ----------------------
__global__ void plan_k() {
    __shared__ int cnt[NEXP], cur[NEXP], base[NEXP];
    int tid = threadIdx.x;
    if (tid < NEXP) { cnt[tid] = 0; cur[tid] = 0; }
    __syncthreads();
    for (int t = tid; t < TOKV; t += blockDim.x) atomicAdd(&cnt[gTokE[t]], 1);
    __syncthreads();
    if (tid == 0) {
        int acc = 0, gc = 0;
        for (int e = 0; e < NEXP; e++) {
            base[e] = acc;
            int ng = (cnt[e] + 255) >> 8;
            for (int i = 0; i < ng && gc < MAXGRP; i++) gGrpE[gc++] = e;
            acc += ng * 256;
        }
        for (; gc < MAXGRP; gc++) gGrpE[gc] = 0;
    }
    __syncthreads();
    for (int r = tid; r < MAXROWS; r += blockDim.x) gRowTok[r] = -1;
    __syncthreads();
    for (int t = tid; t < TOKV; t += blockDim.x) {
        int e = gTokE[t];
        int s = atomicAdd(&cur[e], 1);
        gRowTok[base[e] + s] = t;
    }
}

// ---------------- weight transpose + bf16 split (coalesced) ----------------
// src [E][R][C] f32 -> dst hi/lo [E][C][R] bf16
__global__ void tsplit_k(const float* __restrict__ src, int R, int C, int which) {
    __shared__ float tile[64][65];
    bf16 *dh, *dl;
    if (which == 0)      { dh = gW1h; dl = gW1l; }
    else if (which == 1) { dh = gW2h; dl = gW2l; }
    else                 { dh = gW3h; dl = gW3l; }
    int e = blockIdx.z;
    int c0 = blockIdx.x * 64, r0 = blockIdx.y * 64;
    int tid = threadIdx.x;
    const float* s = src + (size_t)e * R * C;
#pragma unroll
    for (int i = 0; i < 16; i++) {
        int idx = i * 256 + tid;
        int r = idx >> 6, c = idx & 63;
        tile[r][c] = s[(size_t)(r0 + r) * C + c0 + c];
    }
    __syncthreads();
    bf16* dhp = dh + (size_t)e * C * R;
    bf16* dlp = dl + (size_t)e * C * R;
#pragma unroll
    for (int i = 0; i < 8; i++) {
        int idx = i * 256 + tid;
        int c = idx >> 5, rp = idx & 31, r = rp * 2;
        float v0 = tile[r][c], v1 = tile[r + 1][c];
        bf16 h0, l0, h1, l1;
        split2(v0, h0, l0);
        split2(v1, h1, l1);
        __nv_bfloat162 vh; vh.x = h0; vh.y = h1;
        __nv_bfloat162 vl; vl.x = l0; vl.y = l1;
        size_t o = (size_t)(c0 + c) * R + r0 + r;
        *(__nv_bfloat162*)(dhp + o) = vh;
        *(__nv_bfloat162*)(dlp + o) = vl;
    }
}

// ------------------------- gather X + split --------------------------------
__global__ void gather_k(const float* __restrict__ x) {
    int row = blockIdx.x;
    int tok = gRowTok[row];
    for (int k = threadIdx.x; k < DIMV; k += blockDim.x) {
        float v = (tok >= 0) ? x[(size_t)tok * DIMV + k] : 0.f;
        bf16 h, l; split2(v, h, l);
        gXh[(size_t)row * DIMV + k] = h;
        gXl[(size_t)row * DIMV + k] = l;
    }
}

// ===================== tcgen05 GEMM1: 2 tiles x N=128, SwiGLU ==============
// stage (64KB): A0h A0l A1h A1l B1h B1l B2h B2l, 8KB each (128 rows x 64B SW64)
#define G1_STG 65536
#define G1_SMEM (1024 + 2*G1_STG)

#if TC_OK
__device__ __forceinline__ void g1_fill(uint32_t sb, int buf, int kc,
                                        int grp, int e, int nb0, int tid) {
    uint32_t st = sb + 1024 + buf * G1_STG;
#pragma unroll
    for (int i = 0; i < 8; i++) {           // A: 4 regions x 512 chunks
        int id = i * 256 + tid;
        int reg = id >> 9, c2 = id & 511;
        int row = c2 >> 2, cb = c2 & 3;
        uint32_t off = SWZ64((uint32_t)(row * 64 + cb * 16));
        const bf16* srcA = (reg & 1) ? gXl : gXh;
        const bf16* g = srcA + ((size_t)(grp * 256 + (reg >> 1) * 128 + row) * DIMV + kc + cb * 8);
        cp16(st + reg * 8192 + off, g);
    }
#pragma unroll
    for (int i = 0; i < 8; i++) {           // B: 4 regions x 512 chunks
        int id = i * 256 + tid;
        int reg = id >> 9, c2 = id & 511;
        int row = c2 >> 2, cb = c2 & 3;
        uint32_t off = SWZ64((uint32_t)(row * 64 + cb * 16));
        const bf16* srcB = (reg == 0) ? gW1h : (reg == 1) ? gW1l : (reg == 2) ? gW2h : gW2l;
        const bf16* g = srcB + ((size_t)e * HIDV + nb0 + row) * DIMV + kc + cb * 8;
        cp16(st + 32768 + reg * 8192 + off, g);
    }
    cpcommit();
}
#endif

__global__ __launch_bounds__(256) void gemm1_tc() {
#if TC_OK
    extern __shared__ char smem[];
    uint32_t sb = smem_u32(smem);
    int tid = threadIdx.x, wid = tid >> 5, lane = tid & 31;
    int grp = blockIdx.y, nb0 = blockIdx.x * 128;
    int e = gGrpE[grp];

    if (wid == 0) tmem_alloc(sb, 512);
    if (tid == 0) { mbar_init(sb + 8, 1); mbar_init(sb + 16, 1); }
    __syncthreads();
    uint32_t tmem;
    asm volatile("ld.shared.b32 %0, [%1];" : "=r"(tmem) : "r"(sb));

    const int NS = DIMV / KC;  // 24
    g1_fill(sb, 0, 0, grp, e, nb0, tid);

    for (int s = 0; s < NS; s++) {
        if (s + 1 < NS) {
            int nb = (s + 1) & 1;
            if (s + 1 >= 2) mbar_wait(sb + 8 + nb * 8, (((s + 1) >> 1) - 1) & 1);
            g1_fill(sb, nb, (s + 1) * KC, grp, e, nb0, tid);
            asm volatile("cp.async.wait_group 1;\n");
        } else {
            asm volatile("cp.async.wait_group 0;\n");
        }
        __syncthreads();
        if (wid == 0) {
            fence_async_smem();
            if (elect1()) {
                uint32_t st = sb + 1024 + (s & 1) * G1_STG;
                uint64_t dA[2][2];
                dA[0][0] = desc64(st);          dA[0][1] = desc64(st + 8192);
                dA[1][0] = desc64(st + 16384);  dA[1][1] = desc64(st + 24576);
                uint64_t b1h = desc64(st + 32768), b1l = desc64(st + 40960);
                uint64_t b2h = desc64(st + 49152), b2l = desc64(st + 57344);
#pragma unroll
                for (int t = 0; t < 2; t++) {
                    uint32_t D1 = tmem + t * 256, D2 = tmem + t * 256 + 128;
#pragma unroll
                    for (int k = 0; k < 2; k++) {
                        uint32_t en = (s == 0 && k == 0) ? 0u : 1u;
                        uint64_t k2 = (uint64_t)(k * 2);
                        mma_ss(D1, dA[t][0] + k2, b1h + k2, en);
                        mma_ss(D1, dA[t][0] + k2, b1l + k2, 1u);
                        mma_ss(D1, dA[t][1] + k2, b1h + k2, 1u);
                        mma_ss(D2, dA[t][0] + k2, b2h + k2, en);
                        mma_ss(D2, dA[t][0] + k2, b2l + k2, 1u);
                        mma_ss(D2, dA[t][1] + k2, b2h + k2, 1u);
                    }
                }
                mma_commit(sb + 8 + (s & 1) * 8);
            }
        }
    }

    mbar_wait(sb + 8 + ((NS - 1) & 1) * 8, ((NS - 1) >> 1) & 1);
    tm_fence_after();

    {
        int t = wid >> 2;
        uint32_t T = tmem + t * 256;
        int grow = grp * 256 + t * 128 + (wid & 3) * 32 + lane;
        bf16* dh = gUh + (size_t)grow * HIDV + nb0;
        bf16* dl = gUl + (size_t)grow * HIDV + nb0;
#pragma unroll
        for (int p = 0; p < 4; p++) {
            uint32_t r1[32], r2[32];
            ldtm32(r1, T + p * 32);
            ldtm32(r2, T + 128 + p * 32);
            tm_wait_ld();
#pragma unroll
            for (int j = 0; j < 32; j += 2) {
                float h1a = __uint_as_float(r1[j]),     h2a = __uint_as_float(r2[j]);
                float h1b = __uint_as_float(r1[j + 1]), h2b = __uint_as_float(r2[j + 1]);
                float ua = h1a * (1.f / (1.f + expf(-h1a))) * h2a;
                float ub = h1b * (1.f / (1.f + expf(-h1b))) * h2b;
                bf16 ha, la, hb, lb;
                split2(ua, ha, la);
                split2(ub, hb, lb);
                __nv_bfloat162 vh; vh.x = ha; vh.y = hb;
                __nv_bfloat162 vl; vl.x = la; vl.y = lb;
                *(__nv_bfloat162*)(dh + p * 32 + j) = vh;
                *(__nv_bfloat162*)(dl + p * 32 + j) = vl;
            }
        }
    }
    __syncthreads();
    if (tid == 0) { mbar_inval(sb + 8); mbar_inval(sb + 16); }
    __syncthreads();
    if (wid == 0) tmem_dealloc(tmem, 512);
#endif
}

// ===================== tcgen05 GEMM2: 2 tiles x N=128, combine =============
// stage (48KB): A0h A0l A1h A1l (8KB each) + Bh Bl (8KB each)
#define G2_STG 49152
#define G2_SMEM (1024 + 2*G2_STG)

#if TC_OK
__device__ __forceinline__ void g2_fill(uint32_t sb, int buf, int kc,
                                        int grp, int e, int nb0, int tid) {
    uint32_t st = sb + 1024 + buf * G2_STG;
#pragma unroll
    for (int i = 0; i < 8; i++) {           // A
        int id = i * 256 + tid;
        int reg = id >> 9, c2 = id & 511;
        int row = c2 >> 2, cb = c2 & 3;
        uint32_t off = SWZ64((uint32_t)(row * 64 + cb * 16));
        const bf16* srcA = (reg & 1) ? gUl : gUh;
        const bf16* g = srcA + ((size_t)(grp * 256 + (reg >> 1) * 128 + row) * HIDV + kc + cb * 8);
        cp16(st + reg * 8192 + off, g);
    }
#pragma unroll
    for (int i = 0; i < 4; i++) {           // B: 2 regions x 512 chunks
        int id = i * 256 + tid;
        int reg = id >> 9, c2 = id & 511;
        int row = c2 >> 2, cb = c2 & 3;
        uint32_t off = SWZ64((uint32_t)(row * 64 + cb * 16));
        const bf16* srcB = reg ? gW3l : gW3h;
        const bf16* g = srcB + ((size_t)e * DIMV + nb0 + row) * HIDV + kc + cb * 8;
        cp16(st + 32768 + reg * 8192 + off, g);
    }
    cpcommit();
}
#endif

__global__ __launch_bounds__(256) void gemm2_tc(float* __restrict__ out) {
#if TC_OK
    extern __shared__ char smem[];
    uint32_t sb = smem_u32(smem);
    int tid = threadIdx.x, wid = tid >> 5, lane = tid & 31;
    int grp = blockIdx.y, nb0 = blockIdx.x * 128;
    int e = gGrpE[grp];

    if (wid == 0) tmem_alloc(sb, 256);
    if (tid == 0) { mbar_init(sb + 8, 1); mbar_init(sb + 16, 1); }
    __syncthreads();
    uint32_t tmem;
    asm volatile("ld.shared.b32 %0, [%1];" : "=r"(tmem) : "r"(sb));

    const int NS = HIDV / KC;  // 64
    g2_fill(sb, 0, 0, grp, e, nb0, tid);

    for (int s = 0; s < NS; s++) {
        if (s + 1 < NS) {
            int nb = (s + 1) & 1;
            if (s + 1 >= 2) mbar_wait(sb + 8 + nb * 8, (((s + 1) >> 1) - 1) & 1);
            g2_fill(sb, nb, (s + 1) * KC, grp, e, nb0, tid);
            asm volatile("cp.async.wait_group 1;\n");
        } else {
            asm volatile("cp.async.wait_group 0;\n");
        }
        __syncthreads();
        if (wid == 0) {
            fence_async_smem();
            if (elect1()) {
                uint32_t st = sb + 1024 + (s & 1) * G2_STG;
                uint64_t dA[2][2];
                dA[0][0] = desc64(st);          dA[0][1] = desc64(st + 8192);
                dA[1][0] = desc64(st + 16384);  dA[1][1] = desc64(st + 24576);
                uint64_t bh = desc64(st + 32768), bl = desc64(st + 40960);
#pragma unroll
                for (int t = 0; t < 2; t++) {
                    uint32_t D = tmem + t * 128;
#pragma unroll
                    for (int k = 0; k < 2; k++) {
                        uint32_t en = (s == 0 && k == 0) ? 0u : 1u;
                        uint64_t k2 = (uint64_t)(k * 2);
                        mma_ss(D, dA[t][0] + k2, bh + k2, en);
                        mma_ss(D, dA[t][0] + k2, bl + k2, 1u);
                        mma_ss(D, dA[t][1] + k2, bh + k2, 1u);
                    }
                }
                mma_commit(sb + 8 + (s & 1) * 8);
            }
        }
    }

    mbar_wait(sb + 8 + ((NS - 1) & 1) * 8, ((NS - 1) >> 1) & 1);
    tm_fence_after();

    {
        int t = wid >> 2;
        uint32_t T = tmem + t * 128;
        int grow = grp * 256 + t * 128 + (wid & 3) * 32 + lane;
        int tok = gRowTok[grow];
        float p = (tok >= 0) ? gP[tok] : 0.f;
        float* o = (tok >= 0) ? (out + (size_t)tok * DIMV + nb0) : nullptr;
#pragma unroll
        for (int pq = 0; pq < 4; pq++) {
            uint32_t r[32];
            ldtm32(r, T + pq * 32);
            tm_wait_ld();
            if (tok >= 0) {
#pragma unroll
                for (int j = 0; j < 32; j++)
                    o[pq * 32 + j] =
                        __bfloat162float(__float2bfloat16(__uint_as_float(r[j]))) * p;
            }
        }
    }
    __syncthreads();
    if (tid == 0) { mbar_inval(sb + 8); mbar_inval(sb + 16); }
    __syncthreads();
    if (wid == 0) tmem_dealloc(tmem, 256);
#endif
}

// ===================== HMMA fallback path ==================================
#if !TC_OK && defined(__CUDA_ARCH__)
#define HM_OK 1
#else
#define HM_OK 0
#endif
#define HBN 64

#if HM_OK
__device__ __forceinline__ void h1_load(
    bf16* a_h, bf16* a_l, bf16* b1h, bf16* b1l, bf16* b2h, bf16* b2l,
    const bf16* gAh, const bf16* gAl,
    const bf16* gB1h, const bf16* gB1l, const bf16* gB2h, const bf16* gB2l,
    int kc, int tid)
{
#pragma unroll
    for (int i = 0; i < 2; i++) {
        int q = tid * 2 + i, r = q >> 2, ko = (q & 3) * 8;
        size_t go = (size_t)r * DIMV + kc + ko;
        cp16(smem_u32(a_h + r * SROW + ko), gAh + go);
        cp16(smem_u32(a_l + r * SROW + ko), gAl + go);
    }
    {
        int r = tid >> 2, ko = (tid & 3) * 8;
        size_t go = (size_t)r * DIMV + kc + ko;
        cp16(smem_u32(b1h + r * SROW + ko), gB1h + go);
        cp16(smem_u32(b1l + r * SROW + ko), gB1l + go);
        cp16(smem_u32(b2h + r * SROW + ko), gB2h + go);
        cp16(smem_u32(b2l + r * SROW + ko), gB2l + go);
    }
    cpcommit();
}
#endif

__global__ __launch_bounds__(256, 1) void gemm1_hm() {
#if HM_OK
    extern __shared__ bf16 smh[];
    bf16* Ah  = smh;
    bf16* Al  = Ah  + 2 * BM * SROW;
    bf16* B1h = Al  + 2 * BM * SROW;
    bf16* B1l = B1h + 2 * HBN * SROW;
    bf16* B2h = B1l + 2 * HBN * SROW;
    bf16* B2l = B2h + 2 * HBN * SROW;

    int tile = blockIdx.y, nb0 = blockIdx.x * HBN;
    int e = gGrpE[tile >> 1];
    int tid = threadIdx.x, lane = tid & 31, warp = tid >> 5;
    int wm = warp & 3, wn = warp >> 2;
    int g = lane >> 2, t4 = lane & 3;

    const bf16* gAh  = gXh + (size_t)tile * BM * DIMV;
    const bf16* gAl  = gXl + (size_t)tile * BM * DIMV;
    const bf16* gB1h = gW1h + ((size_t)e * HIDV + nb0) * DIMV;
    const bf16* gB1l = gW1l + ((size_t)e * HIDV + nb0) * DIMV;
    const bf16* gB2h = gW2h + ((size_t)e * HIDV + nb0) * DIMV;
    const bf16* gB2l = gW2l + ((size_t)e * HIDV + nb0) * DIMV;

    float acc1[2][4][4], acc2[2][4][4];
#pragma unroll
    for (int m = 0; m < 2; m++)
#pragma unroll
        for (int n = 0; n < 4; n++)
#pragma unroll
            for (int i = 0; i < 4; i++) { acc1[m][n][i] = 0.f; acc2[m][n][i] = 0.f; }

    const int NSTEP = DIMV / BK;
    h1_load(Ah, Al, B1h, B1l, B2h, B2l, gAh, gAl, gB1h, gB1l, gB2h, gB2l, 0, tid);

    for (int s = 0; s < NSTEP; s++) {
        if (s + 1 < NSTEP) {
            int buf = (s + 1) & 1;
            h1_load(Ah + buf * BM * SROW, Al + buf * BM * SROW,
                    B1h + buf * HBN * SROW, B1l + buf * HBN * SROW,
                    B2h + buf * HBN * SROW, B2l + buf * HBN * SROW,
                    gAh, gAl, gB1h, gB1l, gB2h, gB2l, (s + 1) * BK, tid);
            asm volatile("cp.async.wait_group 1;\n");
        } else {
            asm volatile("cp.async.wait_group 0;\n");
        }
        __syncthreads();
        int buf = s & 1;
        const bf16* a_h = Ah  + buf * BM * SROW;
        const bf16* a_l = Al  + buf * BM * SROW;
        const bf16* b1h = B1h + buf * HBN * SROW;
        const bf16* b1l = B1l + buf * HBN * SROW;
        const bf16* b2h = B2h + buf * HBN * SROW;
        const bf16* b2l = B2l + buf * HBN * SROW;

#pragma unroll
        for (int kk = 0; kk < 2; kk++) {
            int kb = kk * 16;
            unsigned Afh[2][4], Afl[2][4];
#pragma unroll
            for (int mt = 0; mt < 2; mt++) {
                int rb = wm * 32 + mt * 16 + g;
                const bf16* p = a_h + rb * SROW + kb + t4 * 2;
                Afh[mt][0] = *(const unsigned*)(p);
                Afh[mt][1] = *(const unsigned*)(p + 8 * SROW);
                Afh[mt][2] = *(const unsigned*)(p + 8);
                Afh[mt][3] = *(const unsigned*)(p + 8 * SROW + 8);
                const bf16* q = a_l + rb * SROW + kb + t4 * 2;
                Afl[mt][0] = *(const unsigned*)(q);
                Afl[mt][1] = *(const unsigned*)(q + 8 * SROW);
                Afl[mt][2] = *(const unsigned*)(q + 8);
                Afl[mt][3] = *(const unsigned*)(q + 8 * SROW + 8);
            }
            {
                unsigned Bh[4][2], Bl[4][2];
#pragma unroll
                for (int nt = 0; nt < 4; nt++) {
                    int nr = wn * 32 + nt * 8 + g;
                    const bf16* p = b1h + nr * SROW + kb + t4 * 2;
                    Bh[nt][0] = *(const unsigned*)(p);
                    Bh[nt][1] = *(const unsigned*)(p + 8);
                    const bf16* q = b1l + nr * SROW + kb + t4 * 2;
                    Bl[nt][0] = *(const unsigned*)(q);
                    Bl[nt][1] = *(const unsigned*)(q + 8);
                }
#pragma unroll
                for (int mt = 0; mt < 2; mt++)
#pragma unroll
                    for (int nt = 0; nt < 4; nt++) {
                        mma_bf16(acc1[mt][nt], Afh[mt], Bh[nt]);
                        mma_bf16(acc1[mt][nt], Afh[mt], Bl[nt]);
                        mma_bf16(acc1[mt][nt], Afl[mt], Bh[nt]);
                    }
            }
            {
                unsigned Bh[4][2], Bl[4][2];
#pragma unroll
                for (int nt = 0; nt < 4; nt++) {
                    int nr = wn * 32 + nt * 8 + g;
                    const bf16* p = b2h + nr * SROW + kb + t4 * 2;
                    Bh[nt][0] = *(const unsigned*)(p);
                    Bh[nt][1] = *(const unsigned*)(p + 8);
                    const bf16* q = b2l + nr * SROW + kb + t4 * 2;
                    Bl[nt][0] = *(const unsigned*)(q);
                    Bl[nt][1] = *(const unsigned*)(q + 8);
                }
#pragma unroll
                for (int mt = 0; mt < 2; mt++)
#pragma unroll
                    for (int nt = 0; nt < 4; nt++) {
                        mma_bf16(acc2[mt][nt], Afh[mt], Bh[nt]);
                        mma_bf16(acc2[mt][nt], Afh[mt], Bl[nt]);
                        mma_bf16(acc2[mt][nt], Afl[mt], Bh[nt]);
                    }
            }
        }
        __syncthreads();
    }

#pragma unroll
    for (int mt = 0; mt < 2; mt++) {
#pragma unroll
        for (int nt = 0; nt < 4; nt++) {
            int lr = wm * 32 + mt * 16 + g;
            int grow = tile * 128 + lr;
            int col = nb0 + wn * 32 + nt * 8 + t4 * 2;
            const float* c1 = acc1[mt][nt];
            const float* c2 = acc2[mt][nt];
#pragma unroll
            for (int half = 0; half < 2; half++) {
                int r = grow + half * 8;
                float h1a = c1[half * 2 + 0], h1b = c1[half * 2 + 1];
                float h2a = c2[half * 2 + 0], h2b = c2[half * 2 + 1];
                float ua = h1a * (1.f / (1.f + expf(-h1a))) * h2a;
                float ub = h1b * (1.f / (1.f + expf(-h1b))) * h2b;
                bf16 ha, la, hb, lb;
                split2(ua, ha, la);
                split2(ub, hb, lb);
                __nv_bfloat162 vh; vh.x = ha; vh.y = hb;
                __nv_bfloat162 vl; vl.x = la; vl.y = lb;
                *(__nv_bfloat162*)(gUh + (size_t)r * HIDV + col) = vh;
                *(__nv_bfloat162*)(gUl + (size_t)r * HIDV + col) = vl;
            }
        }
    }
#endif
}

#if HM_OK
__device__ __forceinline__ void h2_load(
    bf16* a_h, bf16* a_l, bf16* bh, bf16* bl,
    const bf16* gAh, const bf16* gAl, const bf16* gBh, const bf16* gBl,
    int kc, int tid)
{
#pragma unroll
    for (int i = 0; i < 2; i++) {
        int q = tid * 2 + i, r = q >> 2, ko = (q & 3) * 8;
        size_t go = (size_t)r * HIDV + kc + ko;
        cp16(smem_u32(a_h + r * SROW + ko), gAh + go);
        cp16(smem_u32(a_l + r * SROW + ko), gAl + go);
    }
    {
        int r = tid >> 2, ko = (tid & 3) * 8;
        size_t go = (size_t)r * HIDV + kc + ko;
        cp16(smem_u32(bh + r * SROW + ko), gBh + go);
        cp16(smem_u32(bl + r * SROW + ko), gBl + go);
    }
    cpcommit();
}
#endif

__global__ __launch_bounds__(256, 1) void gemm2_hm(float* __restrict__ out) {
#if HM_OK
    extern __shared__ bf16 smh[];
    bf16* Ah = smh;
    bf16* Al = Ah + 2 * BM * SROW;
    bf16* Bh = Al + 2 * BM * SROW;
    bf16* Bl = Bh + 2 * HBN * SROW;

    int tile = blockIdx.y, nb0 = blockIdx.x * HBN;
    int e = gGrpE[tile >> 1];
    int tid = threadIdx.x, lane = tid & 31, warp = tid >> 5;
    int wm = warp & 3, wn = warp >> 2;
    int g = lane >> 2, t4 = lane & 3;

    const bf16* gAh2 = gUh + (size_t)tile * BM * HIDV;
    const bf16* gAl2 = gUl + (size_t)tile * BM * HIDV;
    const bf16* gBh2 = gW3h + ((size_t)e * DIMV + nb0) * HIDV;
    const bf16* gBl2 = gW3l + ((size_t)e * DIMV + nb0) * HIDV;

    float acc[2][4][4];
#pragma unroll
    for (int m = 0; m < 2; m++)
#pragma unroll
        for (int n = 0; n < 4; n++)
#pragma unroll
            for (int i = 0; i < 4; i++) acc[m][n][i] = 0.f;

    const int NSTEP = HIDV / BK;
    h2_load(Ah, Al, Bh, Bl, gAh2, gAl2, gBh2, gBl2, 0, tid);

    for (int s = 0; s < NSTEP; s++) {
        if (s + 1 < NSTEP) {
            int buf = (s + 1) & 1;
            h2_load(Ah + buf * BM * SROW, Al + buf * BM * SROW,
                    Bh + buf * HBN * SROW, Bl + buf * HBN * SROW,
                    gAh2, gAl2, gBh2, gBl2, (s + 1) * BK, tid);
            asm volatile("cp.async.wait_group 1;\n");
        } else {
            asm volatile("cp.async.wait_group 0;\n");
        }
        __syncthreads();
        int buf = s & 1;
        const bf16* a_h = Ah + buf * BM * SROW;
        const bf16* a_l = Al + buf * BM * SROW;
        const bf16* b_h = Bh + buf * HBN * SROW;
        const bf16* b_l = Bl + buf * HBN * SROW;

#pragma unroll
        for (int kk = 0; kk < 2; kk++) {
            int kb = kk * 16;
            unsigned Afh[2][4], Afl[2][4];
#pragma unroll
            for (int mt = 0; mt < 2; mt++) {
                int rb = wm * 32 + mt * 16 + g;
                const bf16* p = a_h + rb * SROW + kb + t4 * 2;
                Afh[mt][0] = *(const unsigned*)(p);
                Afh[mt][1] = *(const unsigned*)(p + 8 * SROW);
                Afh[mt][2] = *(const unsigned*)(p + 8);
                Afh[mt][3] = *(const unsigned*)(p + 8 * SROW + 8);
                const bf16* q = a_l + rb * SROW + kb + t4 * 2;
                Afl[mt][0] = *(const unsigned*)(q);
                Afl[mt][1] = *(const unsigned*)(q + 8 * SROW);
                Afl[mt][2] = *(const unsigned*)(q + 8);
                Afl[mt][3] = *(const unsigned*)(q + 8 * SROW + 8);
            }
            unsigned Bfh[4][2], Bfl[4][2];
#pragma unroll
            for (int nt = 0; nt < 4; nt++) {
                int nr = wn * 32 + nt * 8 + g;
                const bf16* p = b_h + nr * SROW + kb + t4 * 2;
                Bfh[nt][0] = *(const unsigned*)(p);
                Bfh[nt][1] = *(const unsigned*)(p + 8);
                const bf16* q = b_l + nr * SROW + kb + t4 * 2;
                Bfl[nt][0] = *(const unsigned*)(q);
                Bfl[nt][1] = *(const unsigned*)(q + 8);
            }
#pragma unroll
            for (int mt = 0; mt < 2; mt++)
#pragma unroll
                for (int nt = 0; nt < 4; nt++) {
                    mma_bf16(acc[mt][nt], Afh[mt], Bfh[nt]);
                    mma_bf16(acc[mt][nt], Afh[mt], Bfl[nt]);
                    mma_bf16(acc[mt][nt], Afl[mt], Bfh[nt]);
                }
        }
        __syncthreads();
    }

#pragma unroll
    for (int mt = 0; mt < 2; mt++) {
        int lr = wm * 32 + mt * 16 + g;
        int grow = tile * 128 + lr;
        int tokA = gRowTok[grow];
        int tokB = gRowTok[grow + 8];
        float pA = (tokA >= 0) ? gP[tokA] : 0.f;
        float pB = (tokB >= 0) ? gP[tokB] : 0.f;
#pragma unroll
        for (int nt = 0; nt < 4; nt++) {
            int col = nb0 + wn * 32 + nt * 8 + t4 * 2;
            const float* c = acc[mt][nt];
            if (tokA >= 0) {
                out[(size_t)tokA * DIMV + col]     = __bfloat162float(__float2bfloat16(c[0])) * pA;
                out[(size_t)tokA * DIMV + col + 1] = __bfloat162float(__float2bfloat16(c[1])) * pA;
            }
            if (tokB >= 0) {
                out[(size_t)tokB * DIMV + col]     = __bfloat162float(__float2bfloat16(c[2])) * pB;
                out[(size_t)tokB * DIMV + col + 1] = __bfloat162float(__float2bfloat16(c[3])) * pB;
            }
        }
    }
#endif
}

// ------------------------- launcher ----------------------------------------
extern "C" void kernel_launch(void* const* d_in, const int* in_sizes, int n_in,
                              void* d_out, int out_size) {
    const float* x  = (const float*)d_in[0];
    const float* rw = (const float*)d_in[1];
    const float* rb = (const float*)d_in[2];
    const float* w1 = (const float*)d_in[3];
    const float* w2 = (const float*)d_in[4];
    const float* w3 = (const float*)d_in[5];
    float* out = (float*)d_out;

    const int SH1 = (int)((2 * BM * SROW * 2 + 2 * HBN * SROW * 4) * sizeof(bf16));
    const int SH2 = (int)((2 * BM * SROW * 2 + 2 * HBN * SROW * 2) * sizeof(bf16));
    cudaFuncSetAttribute(gemm1_tc, cudaFuncAttributeMaxDynamicSharedMemorySize, G1_SMEM);
    cudaFuncSetAttribute(gemm2_tc, cudaFuncAttributeMaxDynamicSharedMemorySize, G2_SMEM);
    cudaFuncSetAttribute(gemm1_hm, cudaFuncAttributeMaxDynamicSharedMemorySize, SH1);
    cudaFuncSetAttribute(gemm2_hm, cudaFuncAttributeMaxDynamicSharedMemorySize, SH2);

    router_k<<<TOKV / 8, 256>>>(x, rw, rb);
    plan_k<<<1, 512>>>();
    tsplit_k<<<dim3(HIDV / 64, DIMV / 64, NEXP), 256>>>(w1, DIMV, HIDV, 0);
    tsplit_k<<<dim3(HIDV / 64, DIMV / 64, NEXP), 256>>>(w2, DIMV, HIDV, 1);
    tsplit_k<<<dim3(DIMV / 64, HIDV / 64, NEXP), 256>>>(w3, HIDV, DIMV, 2);
    gather_k<<<MAXROWS, 256>>>(x);
    gemm1_tc<<<dim3(HIDV / 128, MAXGRP), 256, G1_SMEM>>>();
    gemm1_hm<<<dim3(HIDV / HBN, NTILE), 256, SH1>>>();
    gemm2_tc<<<dim3(DIMV / 128, MAXGRP), 256, G2_SMEM>>>(out);
    gemm2_hm<<<dim3(DIMV / HBN, NTILE), 256, SH2>>>(out);
}